// round 1
// baseline (speedup 1.0000x reference)
#include <cuda_runtime.h>
#include <math.h>
#include <stdint.h>

#define DMODEL 2048
#define TDMODEL 6144
#define NR 4096      // B*S rows
#define NH 16
#define HD 128
#define SEQ 2048
#define NB 2

// Scratch (no allocations allowed): qkv = 100.7 MB, att = 33.6 MB
__device__ float g_qkv[(size_t)NR * TDMODEL];
__device__ float g_att[(size_t)NR * DMODEL];

// ---------------------------------------------------------------------------
// C[M,N] = A[M,K] * B[N,K]^T   (both row-major, K contiguous -> NT GEMM)
// 128x128 tile, BK=16, 256 threads, 8x8 per-thread microtile (split 4+4).
// ---------------------------------------------------------------------------
__global__ __launch_bounds__(256, 2)
void gemm_nt_kernel(const float* __restrict__ A, const float* __restrict__ B,
                    float* __restrict__ C, int M, int N, int K)
{
    __shared__ float As[16][132];
    __shared__ float Bs[16][132];

    const int tid = threadIdx.x;
    const int tx = tid & 15, ty = tid >> 4;
    const int bm = blockIdx.y * 128, bn = blockIdx.x * 128;

    const float* Ag = A + (size_t)bm * K;
    const float* Bg = B + (size_t)bn * K;

    float acc[8][8];
#pragma unroll
    for (int i = 0; i < 8; i++)
#pragma unroll
        for (int j = 0; j < 8; j++) acc[i][j] = 0.f;

    const int lrow = tid >> 2;          // 0..63
    const int lc4  = (tid & 3) * 4;     // 0,4,8,12

    for (int k0 = 0; k0 < K; k0 += 16) {
#pragma unroll
        for (int h = 0; h < 2; h++) {
            int row = lrow + h * 64;
            float4 va = *(const float4*)(Ag + (size_t)row * K + k0 + lc4);
            As[lc4 + 0][row] = va.x; As[lc4 + 1][row] = va.y;
            As[lc4 + 2][row] = va.z; As[lc4 + 3][row] = va.w;
            float4 vb = *(const float4*)(Bg + (size_t)row * K + k0 + lc4);
            Bs[lc4 + 0][row] = vb.x; Bs[lc4 + 1][row] = vb.y;
            Bs[lc4 + 2][row] = vb.z; Bs[lc4 + 3][row] = vb.w;
        }
        __syncthreads();
#pragma unroll
        for (int k = 0; k < 16; k++) {
            float a[8], b[8];
            *(float4*)(a)     = *(const float4*)&As[k][ty * 4];
            *(float4*)(a + 4) = *(const float4*)&As[k][64 + ty * 4];
            *(float4*)(b)     = *(const float4*)&Bs[k][tx * 4];
            *(float4*)(b + 4) = *(const float4*)&Bs[k][64 + tx * 4];
#pragma unroll
            for (int i = 0; i < 8; i++)
#pragma unroll
                for (int j = 0; j < 8; j++)
                    acc[i][j] = fmaf(a[i], b[j], acc[i][j]);
        }
        __syncthreads();
    }

#pragma unroll
    for (int i = 0; i < 8; i++) {
        int row = bm + ((i < 4) ? (ty * 4 + i) : (64 + ty * 4 + i - 4));
        float* cp = C + (size_t)row * N + bn;
        *(float4*)(cp + tx * 4)      = make_float4(acc[i][0], acc[i][1], acc[i][2], acc[i][3]);
        *(float4*)(cp + 64 + tx * 4) = make_float4(acc[i][4], acc[i][5], acc[i][6], acc[i][7]);
    }
}

// ---------------------------------------------------------------------------
// Causal flash attention, fp32. One block per (q_tile=64, head, batch).
// 256 threads as 16x16 grid: thread (tx,ty) owns score microtile
// rows ty*4..+3, keys tx*4..+3. Online softmax stats per-row held redundantly
// in registers across the 16 lanes of each half-warp (shuffle reductions).
// ---------------------------------------------------------------------------
#define QPAD 132
#define PPAD 68
#define ATTN_SMEM_BYTES ((3 * 64 * QPAD + 64 * PPAD) * 4)

__global__ __launch_bounds__(256, 1)
void attn_kernel(const float* __restrict__ qkv, float* __restrict__ att)
{
    extern __shared__ float sm[];
    float* Qs = sm;                   // [64][132]
    float* Ks = sm + 64 * QPAD;       // [64][132]
    float* Vs = sm + 2 * 64 * QPAD;   // [64][132]
    float* Ps = sm + 3 * 64 * QPAD;   // [64][68]

    const int tid = threadIdx.x;
    const int tx = tid & 15, ty = tid >> 4;
    const int qt = blockIdx.x;        // 0..31
    const int h  = blockIdx.y;
    const int b  = blockIdx.z;
    const int q0 = qt * 64;
    const size_t rowbase = (size_t)b * SEQ;
    const float scale = 0.08838834764831845f;   // 1/sqrt(128)

    // Load Q tile once, pre-scaled.
#pragma unroll
    for (int it = 0; it < 8; it++) {
        int idx = tid + it * 256;
        int r = idx >> 5;
        int d = (idx & 31) * 4;
        float4 v = *(const float4*)(qkv + (rowbase + q0 + r) * TDMODEL + (size_t)h * HD + d);
        v.x *= scale; v.y *= scale; v.z *= scale; v.w *= scale;
        *(float4*)&Qs[r * QPAD + d] = v;
    }

    float m_r[4], l_r[4], o[4][8];
#pragma unroll
    for (int i = 0; i < 4; i++) {
        m_r[i] = -INFINITY; l_r[i] = 0.f;
#pragma unroll
        for (int j = 0; j < 8; j++) o[i][j] = 0.f;
    }

    for (int kt = 0; kt <= qt; kt++) {
        __syncthreads();   // previous tile's V/P reads done before overwrite
#pragma unroll
        for (int it = 0; it < 8; it++) {
            int idx = tid + it * 256;
            int r = idx >> 5;
            int d = (idx & 31) * 4;
            size_t g = (rowbase + kt * 64 + r) * TDMODEL + (size_t)h * HD + d;
            *(float4*)&Ks[r * QPAD + d] = *(const float4*)(qkv + g + DMODEL);
            *(float4*)&Vs[r * QPAD + d] = *(const float4*)(qkv + g + 2 * DMODEL);
        }
        __syncthreads();

        // ---- scores S = Q K^T (Q pre-scaled) ----
        float s[4][4];
#pragma unroll
        for (int i = 0; i < 4; i++)
#pragma unroll
            for (int j = 0; j < 4; j++) s[i][j] = 0.f;

        for (int d = 0; d < HD; d += 4) {
            float4 q4[4], k4[4];
#pragma unroll
            for (int i = 0; i < 4; i++) q4[i] = *(const float4*)&Qs[(ty * 4 + i) * QPAD + d];
#pragma unroll
            for (int j = 0; j < 4; j++) k4[j] = *(const float4*)&Ks[(tx * 4 + j) * QPAD + d];
#pragma unroll
            for (int i = 0; i < 4; i++)
#pragma unroll
                for (int j = 0; j < 4; j++) {
                    s[i][j] = fmaf(q4[i].x, k4[j].x, s[i][j]);
                    s[i][j] = fmaf(q4[i].y, k4[j].y, s[i][j]);
                    s[i][j] = fmaf(q4[i].z, k4[j].z, s[i][j]);
                    s[i][j] = fmaf(q4[i].w, k4[j].w, s[i][j]);
                }
        }

        // causal mask on the diagonal tile only
        if (kt == qt) {
#pragma unroll
            for (int i = 0; i < 4; i++)
#pragma unroll
                for (int j = 0; j < 4; j++)
                    if (tx * 4 + j > ty * 4 + i) s[i][j] = -INFINITY;
        }

        // ---- online softmax (per-row, redundantly across 16-lane group) ----
        float alpha[4];
#pragma unroll
        for (int i = 0; i < 4; i++) {
            float mx = fmaxf(fmaxf(s[i][0], s[i][1]), fmaxf(s[i][2], s[i][3]));
            mx = fmaxf(mx, __shfl_xor_sync(0xffffffffu, mx, 1));
            mx = fmaxf(mx, __shfl_xor_sync(0xffffffffu, mx, 2));
            mx = fmaxf(mx, __shfl_xor_sync(0xffffffffu, mx, 4));
            mx = fmaxf(mx, __shfl_xor_sync(0xffffffffu, mx, 8));
            float mnew = fmaxf(m_r[i], mx);
            alpha[i] = __expf(m_r[i] - mnew);   // -inf -> 0 on first tile
            m_r[i] = mnew;
            float p0 = __expf(s[i][0] - mnew);
            float p1 = __expf(s[i][1] - mnew);
            float p2 = __expf(s[i][2] - mnew);
            float p3 = __expf(s[i][3] - mnew);
            float sum = (p0 + p1) + (p2 + p3);
            sum += __shfl_xor_sync(0xffffffffu, sum, 1);
            sum += __shfl_xor_sync(0xffffffffu, sum, 2);
            sum += __shfl_xor_sync(0xffffffffu, sum, 4);
            sum += __shfl_xor_sync(0xffffffffu, sum, 8);
            l_r[i] = l_r[i] * alpha[i] + sum;
            *(float4*)&Ps[(ty * 4 + i) * PPAD + tx * 4] = make_float4(p0, p1, p2, p3);
#pragma unroll
            for (int c = 0; c < 8; c++) o[i][c] *= alpha[i];
        }
        __syncwarp();   // P rows are written & read within the same warp

        // ---- O += P @ V : rows ty*4..+3, cols {tx*4..+3, 64+tx*4..+3} ----
        for (int j0 = 0; j0 < 64; j0 += 4) {
            float4 p4[4];
#pragma unroll
            for (int i = 0; i < 4; i++) p4[i] = *(const float4*)&Ps[(ty * 4 + i) * PPAD + j0];
#pragma unroll
            for (int jj = 0; jj < 4; jj++) {
                float4 v0 = *(const float4*)&Vs[(j0 + jj) * QPAD + tx * 4];
                float4 v1 = *(const float4*)&Vs[(j0 + jj) * QPAD + 64 + tx * 4];
#pragma unroll
                for (int i = 0; i < 4; i++) {
                    float pp = (jj == 0) ? p4[i].x : (jj == 1) ? p4[i].y : (jj == 2) ? p4[i].z : p4[i].w;
                    o[i][0] = fmaf(pp, v0.x, o[i][0]);
                    o[i][1] = fmaf(pp, v0.y, o[i][1]);
                    o[i][2] = fmaf(pp, v0.z, o[i][2]);
                    o[i][3] = fmaf(pp, v0.w, o[i][3]);
                    o[i][4] = fmaf(pp, v1.x, o[i][4]);
                    o[i][5] = fmaf(pp, v1.y, o[i][5]);
                    o[i][6] = fmaf(pp, v1.z, o[i][6]);
                    o[i][7] = fmaf(pp, v1.w, o[i][7]);
                }
            }
        }
    }

    // epilogue: normalize and store in [n, h*128 + c] layout
#pragma unroll
    for (int i = 0; i < 4; i++) {
        float inv = 1.0f / l_r[i];
        size_t n = rowbase + q0 + ty * 4 + i;
        float* op = att + n * DMODEL + (size_t)h * HD;
        *(float4*)(op + tx * 4) =
            make_float4(o[i][0] * inv, o[i][1] * inv, o[i][2] * inv, o[i][3] * inv);
        *(float4*)(op + 64 + tx * 4) =
            make_float4(o[i][4] * inv, o[i][5] * inv, o[i][6] * inv, o[i][7] * inv);
    }
}

// ---------------------------------------------------------------------------
extern "C" void kernel_launch(void* const* d_in, const int* in_sizes, int n_in,
                              void* d_out, int out_size)
{
    const float* x    = (const float*)d_in[0];   // [2,2048,2048]
    const float* Wqkv = (const float*)d_in[1];   // [6144,2048]
    const float* Wo   = (const float*)d_in[2];   // [2048,2048]
    float* out = (float*)d_out;                  // [2,2048,2048]

    void *qkv_p = nullptr, *att_p = nullptr;
    cudaGetSymbolAddress(&qkv_p, g_qkv);
    cudaGetSymbolAddress(&att_p, g_att);
    float* qkv = (float*)qkv_p;
    float* att = (float*)att_p;

    dim3 blk(256);

    // 1) qkv = x @ Wqkv^T
    gemm_nt_kernel<<<dim3(TDMODEL / 128, NR / 128), blk>>>(x, Wqkv, qkv, NR, TDMODEL, DMODEL);

    // 2) causal attention
    cudaFuncSetAttribute(attn_kernel, cudaFuncAttributeMaxDynamicSharedMemorySize,
                         ATTN_SMEM_BYTES);
    attn_kernel<<<dim3(SEQ / 64, NH, NB), blk, ATTN_SMEM_BYTES>>>(qkv, att);

    // 3) out = att @ Wo^T
    gemm_nt_kernel<<<dim3(DMODEL / 128, NR / 128), blk>>>(att, Wo, out, NR, DMODEL, DMODEL);
}

// round 4
// speedup vs baseline: 1.4497x; 1.4497x over previous
#include <cuda_runtime.h>
#include <cuda_bf16.h>
#include <math.h>
#include <stdint.h>

#define DMODEL 2048
#define TDMODEL 6144
#define NR 4096      // B*S rows
#define NH 16
#define HD 128
#define SEQ 2048
#define NB 2

// ---------------------------------------------------------------------------
// Scratch (no allocations allowed)
// ---------------------------------------------------------------------------
__device__ float g_qkv[(size_t)NR * TDMODEL];          // 100.7 MB
__device__ float g_att[(size_t)NR * DMODEL];           //  33.6 MB
__device__ __nv_bfloat16 g_xh[(size_t)NR * DMODEL];
__device__ __nv_bfloat16 g_xl[(size_t)NR * DMODEL];
__device__ __nv_bfloat16 g_wqkvh[(size_t)TDMODEL * DMODEL];
__device__ __nv_bfloat16 g_wqkvl[(size_t)TDMODEL * DMODEL];
__device__ __nv_bfloat16 g_woh[(size_t)DMODEL * DMODEL];
__device__ __nv_bfloat16 g_wol[(size_t)DMODEL * DMODEL];
__device__ __nv_bfloat16 g_atth[(size_t)NR * DMODEL];
__device__ __nv_bfloat16 g_attl[(size_t)NR * DMODEL];

// ---------------------------------------------------------------------------
// PTX helpers (sm_80+ portable: cp.async, ldmatrix, mma.sync)
// ---------------------------------------------------------------------------
__device__ __forceinline__ uint32_t smem_u32(const void* p) {
    uint32_t a;
    asm("{ .reg .u64 t; cvta.to.shared.u64 t, %1; cvt.u32.u64 %0, t; }" : "=r"(a) : "l"(p));
    return a;
}
__device__ __forceinline__ void cp16(uint32_t dst, const void* src) {
    asm volatile("cp.async.cg.shared.global [%0], [%1], 16;" :: "r"(dst), "l"(src));
}
__device__ __forceinline__ void ldsm_x4(uint32_t addr, uint32_t& r0, uint32_t& r1,
                                        uint32_t& r2, uint32_t& r3) {
    asm volatile("ldmatrix.sync.aligned.m8n8.x4.shared.b16 {%0,%1,%2,%3}, [%4];"
                 : "=r"(r0), "=r"(r1), "=r"(r2), "=r"(r3) : "r"(addr));
}
__device__ __forceinline__ void mma_bf16(float* d, const uint32_t* a,
                                         uint32_t b0, uint32_t b1) {
    asm volatile(
        "mma.sync.aligned.m16n8k16.row.col.f32.bf16.bf16.f32 "
        "{%0,%1,%2,%3}, {%4,%5,%6,%7}, {%8,%9}, {%0,%1,%2,%3};"
        : "+f"(d[0]), "+f"(d[1]), "+f"(d[2]), "+f"(d[3])
        : "r"(a[0]), "r"(a[1]), "r"(a[2]), "r"(a[3]), "r"(b0), "r"(b1));
}

// ---------------------------------------------------------------------------
// Split fp32 -> bf16 hi + bf16 lo (residual)
// ---------------------------------------------------------------------------
__global__ void split_kernel(const float* __restrict__ s,
                             __nv_bfloat16* __restrict__ h,
                             __nv_bfloat16* __restrict__ l, int n4)
{
    int i = blockIdx.x * blockDim.x + threadIdx.x;
    if (i >= n4) return;
    float4 v = ((const float4*)s)[i];
    ushort4 uh, ul;
    __nv_bfloat16 b;
    b = __float2bfloat16(v.x); uh.x = __bfloat16_as_ushort(b);
    ul.x = __bfloat16_as_ushort(__float2bfloat16(v.x - __bfloat162float(b)));
    b = __float2bfloat16(v.y); uh.y = __bfloat16_as_ushort(b);
    ul.y = __bfloat16_as_ushort(__float2bfloat16(v.y - __bfloat162float(b)));
    b = __float2bfloat16(v.z); uh.z = __bfloat16_as_ushort(b);
    ul.z = __bfloat16_as_ushort(__float2bfloat16(v.z - __bfloat162float(b)));
    b = __float2bfloat16(v.w); uh.w = __bfloat16_as_ushort(b);
    ul.w = __bfloat16_as_ushort(__float2bfloat16(v.w - __bfloat162float(b)));
    ((ushort4*)h)[i] = uh;
    ((ushort4*)l)[i] = ul;
}

// ---------------------------------------------------------------------------
// mma.sync NT GEMM:  C[M,N] = (Ah+Al)[M,K] * (Bh+Bl)[N,K]^T   (3-pass split)
// 128x128 tile, BK=32, 256 threads = 8 warps (2x4), warp tile 64x32.
// Double-buffered cp.async; smem row stride 40 bf16 (conflict-free ldmatrix).
// ---------------------------------------------------------------------------
#define GSTRIDE 40                       // bf16 elems per smem row
#define STG ((uint32_t)(128 * GSTRIDE * 2))   // 10240 B per stage per operand
#define OPB (2 * STG)
#define GEMM_SMEM_BYTES (4 * OPB)        // 81920

__global__ __launch_bounds__(256, 1)
void gemm_mma(const __nv_bfloat16* __restrict__ Ah, const __nv_bfloat16* __restrict__ Al,
              const __nv_bfloat16* __restrict__ Bh, const __nv_bfloat16* __restrict__ Bl,
              float* __restrict__ C, int M, int N, int K)
{
    extern __shared__ char smem[];
    const uint32_t sb = smem_u32(smem);
    const uint32_t sAh = sb, sAl = sb + OPB, sBh = sb + 2 * OPB, sBl = sb + 3 * OPB;

    const int tid = threadIdx.x, lane = tid & 31, wid = tid >> 5;
    const int bm = blockIdx.y * 128, bn = blockIdx.x * 128;
    const int m0 = (wid & 1) * 64, n0 = (wid >> 1) * 32;

    const char* gAh = (const char*)(Ah + (size_t)bm * K);
    const char* gAl = (const char*)(Al + (size_t)bm * K);
    const char* gBh = (const char*)(Bh + (size_t)bn * K);
    const char* gBl = (const char*)(Bl + (size_t)bn * K);

    float acc[4][4][4];
#pragma unroll
    for (int i = 0; i < 4; i++)
#pragma unroll
        for (int j = 0; j < 4; j++)
#pragma unroll
            for (int c = 0; c < 4; c++) acc[i][j][c] = 0.f;

    const int lrow = tid >> 2;              // 0..63  (x2 halves -> 128 rows)
    const int lcol = (tid & 3) * 8;         // bf16 col: 0,8,16,24

    // ---- stage loader: 8 cp16 per thread (2 chunks x 4 operands) ----
    auto load_stage = [&](int kb, int buf) {
#pragma unroll
        for (int t = 0; t < 2; t++) {
            int row = lrow + t * 64;
            uint32_t so = (uint32_t)(row * GSTRIDE + lcol) * 2 + buf * STG;
            size_t go = ((size_t)row * K + (size_t)kb * 32 + lcol) * 2;
            cp16(sAh + so, gAh + go);
            cp16(sAl + so, gAl + go);
            cp16(sBh + so, gBh + go);
            cp16(sBl + so, gBl + go);
        }
        asm volatile("cp.async.commit_group;" ::: "memory");
    };

    const int nk = K / 32;
    load_stage(0, 0);

    const int lr = lane & 15, lc = (lane >> 4) * 8;

    for (int kb = 0; kb < nk; kb++) {
        const int buf = kb & 1;
        if (kb + 1 < nk) {
            load_stage(kb + 1, buf ^ 1);
            asm volatile("cp.async.wait_group 1;" ::: "memory");
        } else {
            asm volatile("cp.async.wait_group 0;" ::: "memory");
        }
        __syncthreads();

#pragma unroll
        for (int ks = 0; ks < 2; ks++) {
            uint32_t ah[4][4], al[4][4], bh[2][4], bl[2][4];
#pragma unroll
            for (int mt = 0; mt < 4; mt++) {
                uint32_t off = (uint32_t)((m0 + mt * 16 + lr) * GSTRIDE + ks * 16 + lc) * 2
                               + buf * STG;
                ldsm_x4(sAh + off, ah[mt][0], ah[mt][1], ah[mt][2], ah[mt][3]);
                ldsm_x4(sAl + off, al[mt][0], al[mt][1], al[mt][2], al[mt][3]);
            }
#pragma unroll
            for (int g = 0; g < 2; g++) {
                uint32_t off = (uint32_t)((n0 + g * 16 + lr) * GSTRIDE + ks * 16 + lc) * 2
                               + buf * STG;
                ldsm_x4(sBh + off, bh[g][0], bh[g][1], bh[g][2], bh[g][3]);
                ldsm_x4(sBl + off, bl[g][0], bl[g][1], bl[g][2], bl[g][3]);
            }
#pragma unroll
            for (int mt = 0; mt < 4; mt++)
#pragma unroll
                for (int nt = 0; nt < 4; nt++) {
                    const int g = nt >> 1, p = nt & 1;
                    mma_bf16(acc[mt][nt], ah[mt], bh[g][p], bh[g][p + 2]);
                    mma_bf16(acc[mt][nt], ah[mt], bl[g][p], bl[g][p + 2]);
                    mma_bf16(acc[mt][nt], al[mt], bh[g][p], bh[g][p + 2]);
                }
        }
        __syncthreads();
    }

    // ---- epilogue ----
    const int gr = lane >> 2, gc = (lane & 3) * 2;
#pragma unroll
    for (int mt = 0; mt < 4; mt++)
#pragma unroll
        for (int nt = 0; nt < 4; nt++) {
            int r = bm + m0 + mt * 16 + gr;
            int cix = bn + n0 + nt * 8 + gc;
            *(float2*)&C[(size_t)r * N + cix] =
                make_float2(acc[mt][nt][0], acc[mt][nt][1]);
            *(float2*)&C[(size_t)(r + 8) * N + cix] =
                make_float2(acc[mt][nt][2], acc[mt][nt][3]);
        }
}

// ---------------------------------------------------------------------------
// Causal flash attention, fp32 (unchanged).
// ---------------------------------------------------------------------------
#define QPAD 132
#define PPAD 68
#define ATTN_SMEM_BYTES ((3 * 64 * QPAD + 64 * PPAD) * 4)

__global__ __launch_bounds__(256, 1)
void attn_kernel(const float* __restrict__ qkv, float* __restrict__ att)
{
    extern __shared__ float sm[];
    float* Qs = sm;
    float* Ks = sm + 64 * QPAD;
    float* Vs = sm + 2 * 64 * QPAD;
    float* Ps = sm + 3 * 64 * QPAD;

    const int tid = threadIdx.x;
    const int tx = tid & 15, ty = tid >> 4;
    const int qt = blockIdx.x;
    const int h  = blockIdx.y;
    const int b  = blockIdx.z;
    const int q0 = qt * 64;
    const size_t rowbase = (size_t)b * SEQ;
    const float scale = 0.08838834764831845f;

#pragma unroll
    for (int it = 0; it < 8; it++) {
        int idx = tid + it * 256;
        int r = idx >> 5;
        int d = (idx & 31) * 4;
        float4 v = *(const float4*)(qkv + (rowbase + q0 + r) * TDMODEL + (size_t)h * HD + d);
        v.x *= scale; v.y *= scale; v.z *= scale; v.w *= scale;
        *(float4*)&Qs[r * QPAD + d] = v;
    }

    float m_r[4], l_r[4], o[4][8];
#pragma unroll
    for (int i = 0; i < 4; i++) {
        m_r[i] = -INFINITY; l_r[i] = 0.f;
#pragma unroll
        for (int j = 0; j < 8; j++) o[i][j] = 0.f;
    }

    for (int kt = 0; kt <= qt; kt++) {
        __syncthreads();
#pragma unroll
        for (int it = 0; it < 8; it++) {
            int idx = tid + it * 256;
            int r = idx >> 5;
            int d = (idx & 31) * 4;
            size_t g = (rowbase + kt * 64 + r) * TDMODEL + (size_t)h * HD + d;
            *(float4*)&Ks[r * QPAD + d] = *(const float4*)(qkv + g + DMODEL);
            *(float4*)&Vs[r * QPAD + d] = *(const float4*)(qkv + g + 2 * DMODEL);
        }
        __syncthreads();

        float s[4][4];
#pragma unroll
        for (int i = 0; i < 4; i++)
#pragma unroll
            for (int j = 0; j < 4; j++) s[i][j] = 0.f;

        for (int d = 0; d < HD; d += 4) {
            float4 q4[4], k4[4];
#pragma unroll
            for (int i = 0; i < 4; i++) q4[i] = *(const float4*)&Qs[(ty * 4 + i) * QPAD + d];
#pragma unroll
            for (int j = 0; j < 4; j++) k4[j] = *(const float4*)&Ks[(tx * 4 + j) * QPAD + d];
#pragma unroll
            for (int i = 0; i < 4; i++)
#pragma unroll
                for (int j = 0; j < 4; j++) {
                    s[i][j] = fmaf(q4[i].x, k4[j].x, s[i][j]);
                    s[i][j] = fmaf(q4[i].y, k4[j].y, s[i][j]);
                    s[i][j] = fmaf(q4[i].z, k4[j].z, s[i][j]);
                    s[i][j] = fmaf(q4[i].w, k4[j].w, s[i][j]);
                }
        }

        if (kt == qt) {
#pragma unroll
            for (int i = 0; i < 4; i++)
#pragma unroll
                for (int j = 0; j < 4; j++)
                    if (tx * 4 + j > ty * 4 + i) s[i][j] = -INFINITY;
        }

        float alpha[4];
#pragma unroll
        for (int i = 0; i < 4; i++) {
            float mx = fmaxf(fmaxf(s[i][0], s[i][1]), fmaxf(s[i][2], s[i][3]));
            mx = fmaxf(mx, __shfl_xor_sync(0xffffffffu, mx, 1));
            mx = fmaxf(mx, __shfl_xor_sync(0xffffffffu, mx, 2));
            mx = fmaxf(mx, __shfl_xor_sync(0xffffffffu, mx, 4));
            mx = fmaxf(mx, __shfl_xor_sync(0xffffffffu, mx, 8));
            float mnew = fmaxf(m_r[i], mx);
            alpha[i] = __expf(m_r[i] - mnew);
            m_r[i] = mnew;
            float p0 = __expf(s[i][0] - mnew);
            float p1 = __expf(s[i][1] - mnew);
            float p2 = __expf(s[i][2] - mnew);
            float p3 = __expf(s[i][3] - mnew);
            float sum = (p0 + p1) + (p2 + p3);
            sum += __shfl_xor_sync(0xffffffffu, sum, 1);
            sum += __shfl_xor_sync(0xffffffffu, sum, 2);
            sum += __shfl_xor_sync(0xffffffffu, sum, 4);
            sum += __shfl_xor_sync(0xffffffffu, sum, 8);
            l_r[i] = l_r[i] * alpha[i] + sum;
            *(float4*)&Ps[(ty * 4 + i) * PPAD + tx * 4] = make_float4(p0, p1, p2, p3);
#pragma unroll
            for (int c = 0; c < 8; c++) o[i][c] *= alpha[i];
        }
        __syncwarp();

        for (int j0 = 0; j0 < 64; j0 += 4) {
            float4 p4[4];
#pragma unroll
            for (int i = 0; i < 4; i++) p4[i] = *(const float4*)&Ps[(ty * 4 + i) * PPAD + j0];
#pragma unroll
            for (int jj = 0; jj < 4; jj++) {
                float4 v0 = *(const float4*)&Vs[(j0 + jj) * QPAD + tx * 4];
                float4 v1 = *(const float4*)&Vs[(j0 + jj) * QPAD + 64 + tx * 4];
#pragma unroll
                for (int i = 0; i < 4; i++) {
                    float pp = (jj == 0) ? p4[i].x : (jj == 1) ? p4[i].y : (jj == 2) ? p4[i].z : p4[i].w;
                    o[i][0] = fmaf(pp, v0.x, o[i][0]);
                    o[i][1] = fmaf(pp, v0.y, o[i][1]);
                    o[i][2] = fmaf(pp, v0.z, o[i][2]);
                    o[i][3] = fmaf(pp, v0.w, o[i][3]);
                    o[i][4] = fmaf(pp, v1.x, o[i][4]);
                    o[i][5] = fmaf(pp, v1.y, o[i][5]);
                    o[i][6] = fmaf(pp, v1.z, o[i][6]);
                    o[i][7] = fmaf(pp, v1.w, o[i][7]);
                }
            }
        }
    }

#pragma unroll
    for (int i = 0; i < 4; i++) {
        float inv = 1.0f / l_r[i];
        size_t n = rowbase + q0 + ty * 4 + i;
        float* op = att + n * DMODEL + (size_t)h * HD;
        *(float4*)(op + tx * 4) =
            make_float4(o[i][0] * inv, o[i][1] * inv, o[i][2] * inv, o[i][3] * inv);
        *(float4*)(op + 64 + tx * 4) =
            make_float4(o[i][4] * inv, o[i][5] * inv, o[i][6] * inv, o[i][7] * inv);
    }
}

// ---------------------------------------------------------------------------
extern "C" void kernel_launch(void* const* d_in, const int* in_sizes, int n_in,
                              void* d_out, int out_size)
{
    const float* x    = (const float*)d_in[0];   // [2,2048,2048]
    const float* Wqkv = (const float*)d_in[1];   // [6144,2048]
    const float* Wo   = (const float*)d_in[2];   // [2048,2048]
    float* out = (float*)d_out;                  // [2,2048,2048]

    void *p;
    cudaGetSymbolAddress(&p, g_qkv);   float* qkv = (float*)p;
    cudaGetSymbolAddress(&p, g_att);   float* att = (float*)p;
    cudaGetSymbolAddress(&p, g_xh);    __nv_bfloat16* xh = (__nv_bfloat16*)p;
    cudaGetSymbolAddress(&p, g_xl);    __nv_bfloat16* xl = (__nv_bfloat16*)p;
    cudaGetSymbolAddress(&p, g_wqkvh); __nv_bfloat16* wqh = (__nv_bfloat16*)p;
    cudaGetSymbolAddress(&p, g_wqkvl); __nv_bfloat16* wql = (__nv_bfloat16*)p;
    cudaGetSymbolAddress(&p, g_woh);   __nv_bfloat16* woh = (__nv_bfloat16*)p;
    cudaGetSymbolAddress(&p, g_wol);   __nv_bfloat16* wol = (__nv_bfloat16*)p;
    cudaGetSymbolAddress(&p, g_atth);  __nv_bfloat16* ath = (__nv_bfloat16*)p;
    cudaGetSymbolAddress(&p, g_attl);  __nv_bfloat16* atl = (__nv_bfloat16*)p;

    cudaFuncSetAttribute(gemm_mma, cudaFuncAttributeMaxDynamicSharedMemorySize,
                         GEMM_SMEM_BYTES);
    cudaFuncSetAttribute(attn_kernel, cudaFuncAttributeMaxDynamicSharedMemorySize,
                         ATTN_SMEM_BYTES);

    // 0) split inputs to bf16 hi/lo
    split_kernel<<<(NR * DMODEL / 4 + 255) / 256, 256>>>(x, xh, xl, NR * DMODEL / 4);
    split_kernel<<<(TDMODEL * DMODEL / 4 + 255) / 256, 256>>>(Wqkv, wqh, wql,
                                                              TDMODEL * DMODEL / 4);
    split_kernel<<<(DMODEL * DMODEL / 4 + 255) / 256, 256>>>(Wo, woh, wol,
                                                             DMODEL * DMODEL / 4);

    // 1) qkv = x @ Wqkv^T  (tensor cores via mma.sync)
    gemm_mma<<<dim3(TDMODEL / 128, NR / 128), 256, GEMM_SMEM_BYTES>>>(
        xh, xl, wqh, wql, qkv, NR, TDMODEL, DMODEL);

    // 2) causal attention (fp32 SIMT)
    attn_kernel<<<dim3(SEQ / 64, NH, NB), 256, ATTN_SMEM_BYTES>>>(qkv, att);

    // 3) split attention output, then out = att @ Wo^T
    split_kernel<<<(NR * DMODEL / 4 + 255) / 256, 256>>>(att, ath, atl, NR * DMODEL / 4);
    gemm_mma<<<dim3(DMODEL / 128, NR / 128), 256, GEMM_SMEM_BYTES>>>(
        ath, atl, woh, wol, out, NR, DMODEL, DMODEL);
}

// round 5
// speedup vs baseline: 2.7371x; 1.8881x over previous
#include <cuda_runtime.h>
#include <cuda_bf16.h>
#include <math.h>
#include <stdint.h>

#define DMODEL 2048
#define TDMODEL 6144
#define NR 4096      // B*S rows
#define NH 16
#define HD 128
#define SEQ 2048
#define NB 2

// ---------------------------------------------------------------------------
// Scratch (no allocations allowed)
// ---------------------------------------------------------------------------
__device__ __nv_bfloat16 g_xh[(size_t)NR * DMODEL];
__device__ __nv_bfloat16 g_xl[(size_t)NR * DMODEL];
__device__ __nv_bfloat16 g_wqkvh[(size_t)TDMODEL * DMODEL];
__device__ __nv_bfloat16 g_wqkvl[(size_t)TDMODEL * DMODEL];
__device__ __nv_bfloat16 g_woh[(size_t)DMODEL * DMODEL];
__device__ __nv_bfloat16 g_wol[(size_t)DMODEL * DMODEL];
__device__ __nv_bfloat16 g_qkvh[(size_t)NR * TDMODEL];
__device__ __nv_bfloat16 g_qkvl[(size_t)NR * TDMODEL];
__device__ __nv_bfloat16 g_vth[(size_t)NB * NH * HD * SEQ];   // [b][h][d][tok]
__device__ __nv_bfloat16 g_vtl[(size_t)NB * NH * HD * SEQ];
__device__ __nv_bfloat16 g_ath[(size_t)NR * DMODEL];
__device__ __nv_bfloat16 g_atl[(size_t)NR * DMODEL];

// ---------------------------------------------------------------------------
// PTX helpers (sm_80+ portable)
// ---------------------------------------------------------------------------
__device__ __forceinline__ uint32_t smem_u32(const void* p) {
    uint32_t a;
    asm("{ .reg .u64 t; cvta.to.shared.u64 t, %1; cvt.u32.u64 %0, t; }" : "=r"(a) : "l"(p));
    return a;
}
__device__ __forceinline__ void cp16(uint32_t dst, const void* src) {
    asm volatile("cp.async.cg.shared.global [%0], [%1], 16;" :: "r"(dst), "l"(src));
}
__device__ __forceinline__ void ldsm_x4(uint32_t addr, uint32_t& r0, uint32_t& r1,
                                        uint32_t& r2, uint32_t& r3) {
    asm volatile("ldmatrix.sync.aligned.m8n8.x4.shared.b16 {%0,%1,%2,%3}, [%4];"
                 : "=r"(r0), "=r"(r1), "=r"(r2), "=r"(r3) : "r"(addr));
}
__device__ __forceinline__ void mma_bf16(float* d, const uint32_t* a,
                                         uint32_t b0, uint32_t b1) {
    asm volatile(
        "mma.sync.aligned.m16n8k16.row.col.f32.bf16.bf16.f32 "
        "{%0,%1,%2,%3}, {%4,%5,%6,%7}, {%8,%9}, {%0,%1,%2,%3};"
        : "+f"(d[0]), "+f"(d[1]), "+f"(d[2]), "+f"(d[3])
        : "r"(a[0]), "r"(a[1]), "r"(a[2]), "r"(a[3]), "r"(b0), "r"(b1));
}
__device__ __forceinline__ float ex2f(float x) {
    float y; asm("ex2.approx.f32 %0, %1;" : "=f"(y) : "f"(x)); return y;
}
// pack {lo, hi} fp32 -> bf16x2 (lo in bits [0:16))
__device__ __forceinline__ uint32_t pack2bf(float lo, float hi) {
    uint32_t r;
    asm("cvt.rn.bf16x2.f32 %0, %1, %2;" : "=r"(r) : "f"(hi), "f"(lo));
    return r;
}
__device__ __forceinline__ float bf_hi_f(float v) {       // fp32 value of bf16(v)
    return __bfloat162float(__float2bfloat16(v));
}

// ---------------------------------------------------------------------------
// Split fp32 -> bf16 hi + bf16 lo (residual)
// ---------------------------------------------------------------------------
__global__ void split_kernel(const float* __restrict__ s,
                             __nv_bfloat16* __restrict__ h,
                             __nv_bfloat16* __restrict__ l, int n4)
{
    int i = blockIdx.x * blockDim.x + threadIdx.x;
    if (i >= n4) return;
    float4 v = ((const float4*)s)[i];
    uint2 uh, ul;
    uh.x = pack2bf(v.x, v.y);
    uh.y = pack2bf(v.z, v.w);
    ul.x = pack2bf(v.x - bf_hi_f(v.x), v.y - bf_hi_f(v.y));
    ul.y = pack2bf(v.z - bf_hi_f(v.z), v.w - bf_hi_f(v.w));
    ((uint2*)h)[i] = uh;
    ((uint2*)l)[i] = ul;
}

// ---------------------------------------------------------------------------
// V transpose: qkv[tok][4096 + h*128 + d] -> vt[(b,h)][d][tok]  (bf16 bits)
// ---------------------------------------------------------------------------
__global__ void vtrans_kernel(const ushort* __restrict__ qh, const ushort* __restrict__ ql,
                              ushort* __restrict__ vh, ushort* __restrict__ vl)
{
    __shared__ ushort t0[32][33], t1[32][33];
    const int bh = blockIdx.z, b = bh >> 4, h = bh & 15;
    const int tok0 = blockIdx.x * 32, d0 = blockIdx.y * 32;
    const int tx = threadIdx.x, ty = threadIdx.y;
    const size_t sbase = ((size_t)(b * SEQ + tok0)) * TDMODEL + 2 * DMODEL + h * HD + d0;
#pragma unroll
    for (int i = 0; i < 4; i++) {
        int r = ty + i * 8;
        t0[r][tx] = qh[sbase + (size_t)r * TDMODEL + tx];
        t1[r][tx] = ql[sbase + (size_t)r * TDMODEL + tx];
    }
    __syncthreads();
    const size_t dbase = ((size_t)(bh * HD + d0)) * SEQ + tok0;
#pragma unroll
    for (int i = 0; i < 4; i++) {
        int r = ty + i * 8;
        vh[dbase + (size_t)r * SEQ + tx] = t0[tx][r];
        vl[dbase + (size_t)r * SEQ + tx] = t1[tx][r];
    }
}

// ---------------------------------------------------------------------------
// mma.sync NT GEMM (3-pass bf16 split), templated epilogue (fp32 or bf16 h/l)
// ---------------------------------------------------------------------------
#define GSTRIDE 40
#define STG ((uint32_t)(128 * GSTRIDE * 2))
#define OPB (2 * STG)
#define GEMM_SMEM_BYTES (4 * OPB)        // 81920

template<bool SPLIT>
__global__ __launch_bounds__(256, 2)
void gemm_mma(const __nv_bfloat16* __restrict__ Ah, const __nv_bfloat16* __restrict__ Al,
              const __nv_bfloat16* __restrict__ Bh, const __nv_bfloat16* __restrict__ Bl,
              float* __restrict__ C, __nv_bfloat16* __restrict__ Ch,
              __nv_bfloat16* __restrict__ Cl, int M, int N, int K)
{
    extern __shared__ char smem[];
    const uint32_t sb = smem_u32(smem);
    const uint32_t sAh = sb, sAl = sb + OPB, sBh = sb + 2 * OPB, sBl = sb + 3 * OPB;

    const int tid = threadIdx.x, lane = tid & 31, wid = tid >> 5;
    const int bm = blockIdx.y * 128, bn = blockIdx.x * 128;
    const int m0 = (wid & 1) * 64, n0 = (wid >> 1) * 32;

    const char* gAh = (const char*)(Ah + (size_t)bm * K);
    const char* gAl = (const char*)(Al + (size_t)bm * K);
    const char* gBh = (const char*)(Bh + (size_t)bn * K);
    const char* gBl = (const char*)(Bl + (size_t)bn * K);

    float acc[4][4][4];
#pragma unroll
    for (int i = 0; i < 4; i++)
#pragma unroll
        for (int j = 0; j < 4; j++)
#pragma unroll
            for (int c = 0; c < 4; c++) acc[i][j][c] = 0.f;

    const int lrow = tid >> 2;
    const int lcol = (tid & 3) * 8;

    auto load_stage = [&](int kb, int buf) {
#pragma unroll
        for (int t = 0; t < 2; t++) {
            int row = lrow + t * 64;
            uint32_t so = (uint32_t)(row * GSTRIDE + lcol) * 2 + buf * STG;
            size_t go = ((size_t)row * K + (size_t)kb * 32 + lcol) * 2;
            cp16(sAh + so, gAh + go);
            cp16(sAl + so, gAl + go);
            cp16(sBh + so, gBh + go);
            cp16(sBl + so, gBl + go);
        }
        asm volatile("cp.async.commit_group;" ::: "memory");
    };

    const int nk = K / 32;
    load_stage(0, 0);

    const int lr = lane & 15, lc = (lane >> 4) * 8;

    for (int kb = 0; kb < nk; kb++) {
        const int buf = kb & 1;
        if (kb + 1 < nk) {
            load_stage(kb + 1, buf ^ 1);
            asm volatile("cp.async.wait_group 1;" ::: "memory");
        } else {
            asm volatile("cp.async.wait_group 0;" ::: "memory");
        }
        __syncthreads();

#pragma unroll
        for (int ks = 0; ks < 2; ks++) {
            uint32_t ah[4][4], al[4][4], bh[2][4], bl[2][4];
#pragma unroll
            for (int mt = 0; mt < 4; mt++) {
                uint32_t off = (uint32_t)((m0 + mt * 16 + lr) * GSTRIDE + ks * 16 + lc) * 2
                               + buf * STG;
                ldsm_x4(sAh + off, ah[mt][0], ah[mt][1], ah[mt][2], ah[mt][3]);
                ldsm_x4(sAl + off, al[mt][0], al[mt][1], al[mt][2], al[mt][3]);
            }
#pragma unroll
            for (int g = 0; g < 2; g++) {
                uint32_t off = (uint32_t)((n0 + g * 16 + lr) * GSTRIDE + ks * 16 + lc) * 2
                               + buf * STG;
                ldsm_x4(sBh + off, bh[g][0], bh[g][1], bh[g][2], bh[g][3]);
                ldsm_x4(sBl + off, bl[g][0], bl[g][1], bl[g][2], bl[g][3]);
            }
#pragma unroll
            for (int mt = 0; mt < 4; mt++)
#pragma unroll
                for (int nt = 0; nt < 4; nt++) {
                    const int g = nt >> 1, p = nt & 1;
                    mma_bf16(acc[mt][nt], ah[mt], bh[g][p], bh[g][p + 2]);
                    mma_bf16(acc[mt][nt], ah[mt], bl[g][p], bl[g][p + 2]);
                    mma_bf16(acc[mt][nt], al[mt], bh[g][p], bh[g][p + 2]);
                }
        }
        __syncthreads();
    }

    const int gr = lane >> 2, gc = (lane & 3) * 2;
#pragma unroll
    for (int mt = 0; mt < 4; mt++)
#pragma unroll
        for (int nt = 0; nt < 4; nt++) {
            int r = bm + m0 + mt * 16 + gr;
            int cix = bn + n0 + nt * 8 + gc;
            if (SPLIT) {
#pragma unroll
                for (int half = 0; half < 2; half++) {
                    float v0 = acc[mt][nt][half * 2], v1 = acc[mt][nt][half * 2 + 1];
                    size_t o = (size_t)(r + half * 8) * N + cix;
                    *(uint32_t*)&Ch[o] = pack2bf(v0, v1);
                    *(uint32_t*)&Cl[o] = pack2bf(v0 - bf_hi_f(v0), v1 - bf_hi_f(v1));
                }
            } else {
                *(float2*)&C[(size_t)r * N + cix] =
                    make_float2(acc[mt][nt][0], acc[mt][nt][1]);
                *(float2*)&C[(size_t)(r + 8) * N + cix] =
                    make_float2(acc[mt][nt][2], acc[mt][nt][3]);
            }
        }
}

// ---------------------------------------------------------------------------
// Tensor-core causal flash attention.
// CTA: 128 q rows, 8 warps (16 rows each), k tiles of 64.
// QK single-pass bf16; PV 3-pass hi/lo split. Output -> bf16 hi/lo.
// ---------------------------------------------------------------------------
#define QSTR 136        // bf16 per row (Q, K tiles)
#define VTSTR 72        // bf16 per row (Vt tiles)
#define SM_Q 0
#define SM_K 34816                       // 2 bufs x 17408
#define SM_VT 69632                      // 2 bufs x (18432 h + 18432 l)
#define ATTN_SMEM_BYTES 143360
#define CEXP 0.12751744f                 // log2(e)/sqrt(128)
#define MASKV (-1e30f)

__global__ __launch_bounds__(256, 1)
void attn_mma(const __nv_bfloat16* __restrict__ qkvh,
              const __nv_bfloat16* __restrict__ vth,
              const __nv_bfloat16* __restrict__ vtl,
              __nv_bfloat16* __restrict__ ath, __nv_bfloat16* __restrict__ atl)
{
    extern __shared__ char smem[];
    const uint32_t sb = smem_u32(smem);

    const int tid = threadIdx.x, lane = tid & 31, wid = tid >> 5;
    const int qb = 15 - blockIdx.x;          // long blocks first
    const int h = blockIdx.y, b = blockIdx.z;
    const int wq0 = wid * 16;
    const int lr = lane & 15, lc = (lane >> 4) * 8;
    const int gr = lane >> 2, gc = (lane & 3) * 2;

    const char* gQ = (const char*)qkvh + ((size_t)(b * SEQ + qb * 128)) * (TDMODEL * 2)
                     + h * 256;
    const char* gK = (const char*)qkvh + ((size_t)(b * SEQ)) * (TDMODEL * 2)
                     + DMODEL * 2 + h * 256;
    const char* gVh = (const char*)vth + ((size_t)((b * NH + h) * HD)) * (SEQ * 2);
    const char* gVl = (const char*)vtl + ((size_t)((b * NH + h) * HD)) * (SEQ * 2);

    // ---- prologue: Q tile (group), then stage 0 (group) ----
    {
#pragma unroll
        for (int i = 0; i < 8; i++) {
            int c = tid + i * 256;                 // 2048 chunks
            int row = c >> 4, coff = (c & 15) * 16;
            cp16(sb + SM_Q + row * (QSTR * 2) + coff, gQ + (size_t)row * 12288 + coff);
        }
        asm volatile("cp.async.commit_group;" ::: "memory");
    }
    auto load_stage = [&](int kt, int buf) {
        const uint32_t kb_ = sb + SM_K + buf * 17408;
        const uint32_t vb_ = sb + SM_VT + buf * 36864;
#pragma unroll
        for (int i = 0; i < 4; i++) {
            int c = tid + i * 256;                 // 1024 chunks (K: 64 rows x 16)
            int row = c >> 4, coff = (c & 15) * 16;
            cp16(kb_ + row * (QSTR * 2) + coff,
                 gK + (size_t)(kt * 64 + row) * 12288 + coff);
        }
#pragma unroll
        for (int i = 0; i < 4; i++) {
            int c = tid + i * 256;                 // 1024 chunks (Vt: 128 rows x 8)
            int row = c >> 3, coff = (c & 7) * 16;
            size_t go = (size_t)row * (SEQ * 2) + (size_t)kt * 128 + coff;
            cp16(vb_ + row * (VTSTR * 2) + coff, gVh + go);
            cp16(vb_ + 18432 + row * (VTSTR * 2) + coff, gVl + go);
        }
        asm volatile("cp.async.commit_group;" ::: "memory");
    };
    load_stage(0, 0);

    uint32_t qf[8][4];
    float acc_o[8][2][4];
#pragma unroll
    for (int gd = 0; gd < 8; gd++)
#pragma unroll
        for (int p = 0; p < 2; p++)
#pragma unroll
            for (int c = 0; c < 4; c++) acc_o[gd][p][c] = 0.f;
    float m0 = MASKV, m1 = MASKV, l0 = 0.f, l1 = 0.f;

    const int ktmax = 2 * qb + 1;
    const int q_row0 = qb * 128 + wq0 + gr;        // this thread's row (and +8)

    for (int kt = 0; kt <= ktmax; kt++) {
        const int buf = kt & 1;
        if (kt < ktmax) {
            load_stage(kt + 1, buf ^ 1);
            asm volatile("cp.async.wait_group 1;" ::: "memory");
        } else {
            asm volatile("cp.async.wait_group 0;" ::: "memory");
        }
        __syncthreads();

        if (kt == 0) {                             // Q fragments (data ready now)
#pragma unroll
            for (int dc = 0; dc < 8; dc++) {
                uint32_t off = sb + SM_Q + (uint32_t)((wq0 + lr) * QSTR + dc * 16 + lc) * 2;
                ldsm_x4(off, qf[dc][0], qf[dc][1], qf[dc][2], qf[dc][3]);
            }
        }

        const uint32_t kb_ = sb + SM_K + buf * 17408;
        const uint32_t vb_ = sb + SM_VT + buf * 36864;

        // ---- S = Q K^T ----
        float s[4][2][4];
#pragma unroll
        for (int g = 0; g < 4; g++)
#pragma unroll
            for (int p = 0; p < 2; p++)
#pragma unroll
                for (int c = 0; c < 4; c++) s[g][p][c] = 0.f;
#pragma unroll
        for (int dc = 0; dc < 8; dc++)
#pragma unroll
            for (int g = 0; g < 4; g++) {
                uint32_t kbt[4];
                ldsm_x4(kb_ + (uint32_t)((g * 16 + lr) * QSTR + dc * 16 + lc) * 2,
                        kbt[0], kbt[1], kbt[2], kbt[3]);
                mma_bf16(s[g][0], qf[dc], kbt[0], kbt[2]);
                mma_bf16(s[g][1], qf[dc], kbt[1], kbt[3]);
            }

        // ---- causal mask (last two tiles only) ----
        if (kt >= 2 * qb) {
#pragma unroll
            for (int g = 0; g < 4; g++)
#pragma unroll
                for (int p = 0; p < 2; p++) {
                    int key = kt * 64 + g * 16 + p * 8 + gc;
                    if (key > q_row0)     s[g][p][0] = MASKV;
                    if (key + 1 > q_row0) s[g][p][1] = MASKV;
                    if (key > q_row0 + 8)     s[g][p][2] = MASKV;
                    if (key + 1 > q_row0 + 8) s[g][p][3] = MASKV;
                }
        }

        // ---- online softmax ----
        float t0 = MASKV, t1 = MASKV;
#pragma unroll
        for (int g = 0; g < 4; g++)
#pragma unroll
            for (int p = 0; p < 2; p++) {
                t0 = fmaxf(t0, fmaxf(s[g][p][0], s[g][p][1]));
                t1 = fmaxf(t1, fmaxf(s[g][p][2], s[g][p][3]));
            }
        t0 = fmaxf(t0, __shfl_xor_sync(0xffffffffu, t0, 1));
        t0 = fmaxf(t0, __shfl_xor_sync(0xffffffffu, t0, 2));
        t1 = fmaxf(t1, __shfl_xor_sync(0xffffffffu, t1, 1));
        t1 = fmaxf(t1, __shfl_xor_sync(0xffffffffu, t1, 2));
        float mn0 = fmaxf(m0, t0), mn1 = fmaxf(m1, t1);
        float a0 = ex2f((m0 - mn0) * CEXP), a1 = ex2f((m1 - mn1) * CEXP);
        m0 = mn0; m1 = mn1;

        uint32_t pah[4][4], pal[4][4];
        float sum0 = 0.f, sum1 = 0.f;
#pragma unroll
        for (int g = 0; g < 4; g++)
#pragma unroll
            for (int p = 0; p < 2; p++) {
                float p0 = ex2f((s[g][p][0] - mn0) * CEXP);
                float p1 = ex2f((s[g][p][1] - mn0) * CEXP);
                float p2 = ex2f((s[g][p][2] - mn1) * CEXP);
                float p3 = ex2f((s[g][p][3] - mn1) * CEXP);
                sum0 += p0 + p1; sum1 += p2 + p3;
                pah[g][2 * p]     = pack2bf(p0, p1);
                pah[g][2 * p + 1] = pack2bf(p2, p3);
                pal[g][2 * p]     = pack2bf(p0 - bf_hi_f(p0), p1 - bf_hi_f(p1));
                pal[g][2 * p + 1] = pack2bf(p2 - bf_hi_f(p2), p3 - bf_hi_f(p3));
            }
        sum0 += __shfl_xor_sync(0xffffffffu, sum0, 1);
        sum0 += __shfl_xor_sync(0xffffffffu, sum0, 2);
        sum1 += __shfl_xor_sync(0xffffffffu, sum1, 1);
        sum1 += __shfl_xor_sync(0xffffffffu, sum1, 2);
        l0 = l0 * a0 + sum0;
        l1 = l1 * a1 + sum1;

#pragma unroll
        for (int gd = 0; gd < 8; gd++)
#pragma unroll
            for (int p = 0; p < 2; p++) {
                acc_o[gd][p][0] *= a0; acc_o[gd][p][1] *= a0;
                acc_o[gd][p][2] *= a1; acc_o[gd][p][3] *= a1;
            }

        // ---- O += P V  (3-pass) ----
#pragma unroll
        for (int kc = 0; kc < 4; kc++)
#pragma unroll
            for (int gd = 0; gd < 8; gd++) {
                uint32_t off = (uint32_t)((gd * 16 + lr) * VTSTR + kc * 16 + lc) * 2;
                uint32_t bvh[4], bvl[4];
                ldsm_x4(vb_ + off, bvh[0], bvh[1], bvh[2], bvh[3]);
                ldsm_x4(vb_ + 18432 + off, bvl[0], bvl[1], bvl[2], bvl[3]);
                mma_bf16(acc_o[gd][0], pah[kc], bvh[0], bvh[2]);
                mma_bf16(acc_o[gd][1], pah[kc], bvh[1], bvh[3]);
                mma_bf16(acc_o[gd][0], pah[kc], bvl[0], bvl[2]);
                mma_bf16(acc_o[gd][1], pah[kc], bvl[1], bvl[3]);
                mma_bf16(acc_o[gd][0], pal[kc], bvh[0], bvh[2]);
                mma_bf16(acc_o[gd][1], pal[kc], bvh[1], bvh[3]);
            }
        __syncthreads();
    }

    // ---- epilogue: normalize, split to bf16 h/l, store ----
    const float i0 = 1.f / l0, i1 = 1.f / l1;
    const size_t tok0 = (size_t)b * SEQ + qb * 128 + wq0 + gr;
#pragma unroll
    for (int gd = 0; gd < 8; gd++)
#pragma unroll
        for (int p = 0; p < 2; p++) {
            int col = h * HD + gd * 16 + p * 8 + gc;
            float v0 = acc_o[gd][p][0] * i0, v1 = acc_o[gd][p][1] * i0;
            float v2 = acc_o[gd][p][2] * i1, v3 = acc_o[gd][p][3] * i1;
            size_t o0 = tok0 * DMODEL + col, o1 = (tok0 + 8) * DMODEL + col;
            *(uint32_t*)&ath[o0] = pack2bf(v0, v1);
            *(uint32_t*)&atl[o0] = pack2bf(v0 - bf_hi_f(v0), v1 - bf_hi_f(v1));
            *(uint32_t*)&ath[o1] = pack2bf(v2, v3);
            *(uint32_t*)&atl[o1] = pack2bf(v2 - bf_hi_f(v2), v3 - bf_hi_f(v3));
        }
}

// ---------------------------------------------------------------------------
extern "C" void kernel_launch(void* const* d_in, const int* in_sizes, int n_in,
                              void* d_out, int out_size)
{
    const float* x    = (const float*)d_in[0];
    const float* Wqkv = (const float*)d_in[1];
    const float* Wo   = (const float*)d_in[2];
    float* out = (float*)d_out;

    void* p;
    cudaGetSymbolAddress(&p, g_xh);    __nv_bfloat16* xh = (__nv_bfloat16*)p;
    cudaGetSymbolAddress(&p, g_xl);    __nv_bfloat16* xl = (__nv_bfloat16*)p;
    cudaGetSymbolAddress(&p, g_wqkvh); __nv_bfloat16* wqh = (__nv_bfloat16*)p;
    cudaGetSymbolAddress(&p, g_wqkvl); __nv_bfloat16* wql = (__nv_bfloat16*)p;
    cudaGetSymbolAddress(&p, g_woh);   __nv_bfloat16* woh = (__nv_bfloat16*)p;
    cudaGetSymbolAddress(&p, g_wol);   __nv_bfloat16* wol = (__nv_bfloat16*)p;
    cudaGetSymbolAddress(&p, g_qkvh);  __nv_bfloat16* qvh = (__nv_bfloat16*)p;
    cudaGetSymbolAddress(&p, g_qkvl);  __nv_bfloat16* qvl = (__nv_bfloat16*)p;
    cudaGetSymbolAddress(&p, g_vth);   __nv_bfloat16* vth = (__nv_bfloat16*)p;
    cudaGetSymbolAddress(&p, g_vtl);   __nv_bfloat16* vtl = (__nv_bfloat16*)p;
    cudaGetSymbolAddress(&p, g_ath);   __nv_bfloat16* ath = (__nv_bfloat16*)p;
    cudaGetSymbolAddress(&p, g_atl);   __nv_bfloat16* atl = (__nv_bfloat16*)p;

    cudaFuncSetAttribute(gemm_mma<true>, cudaFuncAttributeMaxDynamicSharedMemorySize,
                         GEMM_SMEM_BYTES);
    cudaFuncSetAttribute(gemm_mma<false>, cudaFuncAttributeMaxDynamicSharedMemorySize,
                         GEMM_SMEM_BYTES);
    cudaFuncSetAttribute(attn_mma, cudaFuncAttributeMaxDynamicSharedMemorySize,
                         ATTN_SMEM_BYTES);

    // 0) split inputs
    split_kernel<<<(NR * DMODEL / 4 + 255) / 256, 256>>>(x, xh, xl, NR * DMODEL / 4);
    split_kernel<<<(TDMODEL * DMODEL / 4 + 255) / 256, 256>>>(Wqkv, wqh, wql,
                                                              TDMODEL * DMODEL / 4);
    split_kernel<<<(DMODEL * DMODEL / 4 + 255) / 256, 256>>>(Wo, woh, wol,
                                                             DMODEL * DMODEL / 4);

    // 1) qkv = x @ Wqkv^T  -> bf16 hi/lo directly
    gemm_mma<true><<<dim3(TDMODEL / 128, NR / 128), 256, GEMM_SMEM_BYTES>>>(
        xh, xl, wqh, wql, nullptr, qvh, qvl, NR, TDMODEL, DMODEL);

    // 2) transpose V panels
    vtrans_kernel<<<dim3(SEQ / 32, HD / 32, NB * NH), dim3(32, 8)>>>(
        (const ushort*)qvh, (const ushort*)qvl, (ushort*)vth, (ushort*)vtl);

    // 3) attention -> bf16 hi/lo
    attn_mma<<<dim3(16, NH, NB), 256, ATTN_SMEM_BYTES>>>(qvh, vth, vtl, ath, atl);

    // 4) out = att @ Wo^T (fp32 out)
    gemm_mma<false><<<dim3(DMODEL / 128, NR / 128), 256, GEMM_SMEM_BYTES>>>(
        ath, atl, woh, wol, out, nullptr, nullptr, NR, DMODEL, DMODEL);
}

// round 6
// speedup vs baseline: 3.4738x; 1.2691x over previous
#include <cuda_runtime.h>
#include <cuda_bf16.h>
#include <math.h>
#include <stdint.h>

#define DMODEL 2048
#define TDMODEL 6144
#define NR 4096      // B*S rows
#define NH 16
#define HD 128
#define SEQ 2048
#define NB 2

// ---------------------------------------------------------------------------
// Scratch (no allocations allowed)
// ---------------------------------------------------------------------------
__device__ __nv_bfloat16 g_xh[(size_t)NR * DMODEL];
__device__ __nv_bfloat16 g_xl[(size_t)NR * DMODEL];
__device__ __nv_bfloat16 g_wqkvh[(size_t)TDMODEL * DMODEL];
__device__ __nv_bfloat16 g_wqkvl[(size_t)TDMODEL * DMODEL];
__device__ __nv_bfloat16 g_woh[(size_t)DMODEL * DMODEL];
__device__ __nv_bfloat16 g_wol[(size_t)DMODEL * DMODEL];
__device__ __nv_bfloat16 g_qkvh[(size_t)NR * TDMODEL];
__device__ __nv_bfloat16 g_qkvl[(size_t)NR * TDMODEL];
__device__ __nv_bfloat16 g_vth[(size_t)NB * NH * HD * SEQ];   // [b][h][d][tok]
__device__ __nv_bfloat16 g_vtl[(size_t)NB * NH * HD * SEQ];
__device__ __nv_bfloat16 g_ath[(size_t)NR * DMODEL];
__device__ __nv_bfloat16 g_atl[(size_t)NR * DMODEL];

// ---------------------------------------------------------------------------
// PTX helpers (sm_80+ portable)
// ---------------------------------------------------------------------------
__device__ __forceinline__ uint32_t smem_u32(const void* p) {
    uint32_t a;
    asm("{ .reg .u64 t; cvta.to.shared.u64 t, %1; cvt.u32.u64 %0, t; }" : "=r"(a) : "l"(p));
    return a;
}
__device__ __forceinline__ void cp16(uint32_t dst, const void* src) {
    asm volatile("cp.async.cg.shared.global [%0], [%1], 16;" :: "r"(dst), "l"(src));
}
__device__ __forceinline__ void ldsm_x4(uint32_t addr, uint32_t& r0, uint32_t& r1,
                                        uint32_t& r2, uint32_t& r3) {
    asm volatile("ldmatrix.sync.aligned.m8n8.x4.shared.b16 {%0,%1,%2,%3}, [%4];"
                 : "=r"(r0), "=r"(r1), "=r"(r2), "=r"(r3) : "r"(addr));
}
__device__ __forceinline__ void mma_bf16(float* d, const uint32_t* a,
                                         uint32_t b0, uint32_t b1) {
    asm volatile(
        "mma.sync.aligned.m16n8k16.row.col.f32.bf16.bf16.f32 "
        "{%0,%1,%2,%3}, {%4,%5,%6,%7}, {%8,%9}, {%0,%1,%2,%3};"
        : "+f"(d[0]), "+f"(d[1]), "+f"(d[2]), "+f"(d[3])
        : "r"(a[0]), "r"(a[1]), "r"(a[2]), "r"(a[3]), "r"(b0), "r"(b1));
}
__device__ __forceinline__ float ex2f(float x) {
    float y; asm("ex2.approx.f32 %0, %1;" : "=f"(y) : "f"(x)); return y;
}
// pack {lo, hi} fp32 -> bf16x2 (lo in bits [0:16))
__device__ __forceinline__ uint32_t pack2bf(float lo, float hi) {
    uint32_t r;
    asm("cvt.rn.bf16x2.f32 %0, %1, %2;" : "=r"(r) : "f"(hi), "f"(lo));
    return r;
}
__device__ __forceinline__ float bf_hi_f(float v) {
    return __bfloat162float(__float2bfloat16(v));
}

// ---------------------------------------------------------------------------
// Split fp32 -> bf16 hi + bf16 lo (residual)
// ---------------------------------------------------------------------------
__global__ void split_kernel(const float* __restrict__ s,
                             __nv_bfloat16* __restrict__ h,
                             __nv_bfloat16* __restrict__ l, int n4)
{
    int i = blockIdx.x * blockDim.x + threadIdx.x;
    if (i >= n4) return;
    float4 v = ((const float4*)s)[i];
    uint2 uh, ul;
    uh.x = pack2bf(v.x, v.y);
    uh.y = pack2bf(v.z, v.w);
    ul.x = pack2bf(v.x - bf_hi_f(v.x), v.y - bf_hi_f(v.y));
    ul.y = pack2bf(v.z - bf_hi_f(v.z), v.w - bf_hi_f(v.w));
    ((uint2*)h)[i] = uh;
    ((uint2*)l)[i] = ul;
}

// ---------------------------------------------------------------------------
// V transpose: qkv[tok][4096 + h*128 + d] -> vt[(b,h)][d][tok]  (bf16 bits)
// ---------------------------------------------------------------------------
__global__ void vtrans_kernel(const ushort* __restrict__ qh, const ushort* __restrict__ ql,
                              ushort* __restrict__ vh, ushort* __restrict__ vl)
{
    __shared__ ushort t0[32][33], t1[32][33];
    const int bh = blockIdx.z, b = bh >> 4, h = bh & 15;
    const int tok0 = blockIdx.x * 32, d0 = blockIdx.y * 32;
    const int tx = threadIdx.x, ty = threadIdx.y;
    const size_t sbase = ((size_t)(b * SEQ + tok0)) * TDMODEL + 2 * DMODEL + h * HD + d0;
#pragma unroll
    for (int i = 0; i < 4; i++) {
        int r = ty + i * 8;
        t0[r][tx] = qh[sbase + (size_t)r * TDMODEL + tx];
        t1[r][tx] = ql[sbase + (size_t)r * TDMODEL + tx];
    }
    __syncthreads();
    const size_t dbase = ((size_t)(bh * HD + d0)) * SEQ + tok0;
#pragma unroll
    for (int i = 0; i < 4; i++) {
        int r = ty + i * 8;
        vh[dbase + (size_t)r * SEQ + tx] = t0[tx][r];
        vl[dbase + (size_t)r * SEQ + tx] = t1[tx][r];
    }
}

// ---------------------------------------------------------------------------
// mma.sync NT GEMM, NPASS = 1 (hi*hi) or 3 (hi*hi + hi*lo + lo*hi).
// 128x128 tile, BK=32, 8 warps (2x4), warp tile 64x32, double-buffered.
// Output slice written at column offset via ldc (row stride of C).
// ---------------------------------------------------------------------------
#define GSTRIDE 40
#define STG ((uint32_t)(128 * GSTRIDE * 2))
#define OPB (2 * STG)

template<bool SPLIT, int NPASS>
__global__ __launch_bounds__(256, 2)
void gemm_mma(const __nv_bfloat16* __restrict__ Ah, const __nv_bfloat16* __restrict__ Al,
              const __nv_bfloat16* __restrict__ Bh, const __nv_bfloat16* __restrict__ Bl,
              float* __restrict__ C, __nv_bfloat16* __restrict__ Ch,
              __nv_bfloat16* __restrict__ Cl, int ldc, int K)
{
    extern __shared__ char smem[];
    const uint32_t sb = smem_u32(smem);
    const uint32_t sAh = sb;
    const uint32_t sBh = sb + (NPASS == 3 ? 2 : 1) * OPB;
    const uint32_t sAl = sb + OPB;             // valid only when NPASS==3
    const uint32_t sBl = sBh + OPB;

    const int tid = threadIdx.x, lane = tid & 31, wid = tid >> 5;
    const int bm = blockIdx.y * 128, bn = blockIdx.x * 128;
    const int m0 = (wid & 1) * 64, n0 = (wid >> 1) * 32;

    const char* gAh = (const char*)(Ah + (size_t)bm * K);
    const char* gAl = (const char*)(Al + (size_t)bm * K);
    const char* gBh = (const char*)(Bh + (size_t)bn * K);
    const char* gBl = (const char*)(Bl + (size_t)bn * K);

    float acc[4][4][4];
#pragma unroll
    for (int i = 0; i < 4; i++)
#pragma unroll
        for (int j = 0; j < 4; j++)
#pragma unroll
            for (int c = 0; c < 4; c++) acc[i][j][c] = 0.f;

    const int lrow = tid >> 2;
    const int lcol = (tid & 3) * 8;

    auto load_stage = [&](int kb, int buf) {
#pragma unroll
        for (int t = 0; t < 2; t++) {
            int row = lrow + t * 64;
            uint32_t so = (uint32_t)(row * GSTRIDE + lcol) * 2 + buf * STG;
            size_t go = ((size_t)row * K + (size_t)kb * 32 + lcol) * 2;
            cp16(sAh + so, gAh + go);
            cp16(sBh + so, gBh + go);
            if (NPASS == 3) {
                cp16(sAl + so, gAl + go);
                cp16(sBl + so, gBl + go);
            }
        }
        asm volatile("cp.async.commit_group;" ::: "memory");
    };

    const int nk = K / 32;
    load_stage(0, 0);

    const int lr = lane & 15, lc = (lane >> 4) * 8;

    for (int kb = 0; kb < nk; kb++) {
        const int buf = kb & 1;
        if (kb + 1 < nk) {
            load_stage(kb + 1, buf ^ 1);
            asm volatile("cp.async.wait_group 1;" ::: "memory");
        } else {
            asm volatile("cp.async.wait_group 0;" ::: "memory");
        }
        __syncthreads();

#pragma unroll
        for (int ks = 0; ks < 2; ks++) {
            uint32_t ah[4][4], al[4][4], bh[2][4], bl[2][4];
#pragma unroll
            for (int mt = 0; mt < 4; mt++) {
                uint32_t off = (uint32_t)((m0 + mt * 16 + lr) * GSTRIDE + ks * 16 + lc) * 2
                               + buf * STG;
                ldsm_x4(sAh + off, ah[mt][0], ah[mt][1], ah[mt][2], ah[mt][3]);
                if (NPASS == 3)
                    ldsm_x4(sAl + off, al[mt][0], al[mt][1], al[mt][2], al[mt][3]);
            }
#pragma unroll
            for (int g = 0; g < 2; g++) {
                uint32_t off = (uint32_t)((n0 + g * 16 + lr) * GSTRIDE + ks * 16 + lc) * 2
                               + buf * STG;
                ldsm_x4(sBh + off, bh[g][0], bh[g][1], bh[g][2], bh[g][3]);
                if (NPASS == 3)
                    ldsm_x4(sBl + off, bl[g][0], bl[g][1], bl[g][2], bl[g][3]);
            }
#pragma unroll
            for (int mt = 0; mt < 4; mt++)
#pragma unroll
                for (int nt = 0; nt < 4; nt++) {
                    const int g = nt >> 1, p = nt & 1;
                    mma_bf16(acc[mt][nt], ah[mt], bh[g][p], bh[g][p + 2]);
                    if (NPASS == 3) {
                        mma_bf16(acc[mt][nt], ah[mt], bl[g][p], bl[g][p + 2]);
                        mma_bf16(acc[mt][nt], al[mt], bh[g][p], bh[g][p + 2]);
                    }
                }
        }
        __syncthreads();
    }

    const int gr = lane >> 2, gc = (lane & 3) * 2;
#pragma unroll
    for (int mt = 0; mt < 4; mt++)
#pragma unroll
        for (int nt = 0; nt < 4; nt++) {
            int r = bm + m0 + mt * 16 + gr;
            int cix = bn + n0 + nt * 8 + gc;
            if (SPLIT) {
#pragma unroll
                for (int half = 0; half < 2; half++) {
                    float v0 = acc[mt][nt][half * 2], v1 = acc[mt][nt][half * 2 + 1];
                    size_t o = (size_t)(r + half * 8) * ldc + cix;
                    *(uint32_t*)&Ch[o] = pack2bf(v0, v1);
                    *(uint32_t*)&Cl[o] = pack2bf(v0 - bf_hi_f(v0), v1 - bf_hi_f(v1));
                }
            } else {
                *(float2*)&C[(size_t)r * ldc + cix] =
                    make_float2(acc[mt][nt][0], acc[mt][nt][1]);
                *(float2*)&C[(size_t)(r + 8) * ldc + cix] =
                    make_float2(acc[mt][nt][2], acc[mt][nt][3]);
            }
        }
}

// ---------------------------------------------------------------------------
// Tensor-core causal flash attention (unchanged from R5).
// ---------------------------------------------------------------------------
#define QSTR 136
#define VTSTR 72
#define SM_Q 0
#define SM_K 34816
#define SM_VT 69632
#define ATTN_SMEM_BYTES 143360
#define CEXP 0.12751744f                 // log2(e)/sqrt(128)
#define MASKV (-1e30f)

__global__ __launch_bounds__(256, 1)
void attn_mma(const __nv_bfloat16* __restrict__ qkvh,
              const __nv_bfloat16* __restrict__ vth,
              const __nv_bfloat16* __restrict__ vtl,
              __nv_bfloat16* __restrict__ ath, __nv_bfloat16* __restrict__ atl)
{
    extern __shared__ char smem[];
    const uint32_t sb = smem_u32(smem);

    const int tid = threadIdx.x, lane = tid & 31, wid = tid >> 5;
    const int qb = 15 - blockIdx.x;
    const int h = blockIdx.y, b = blockIdx.z;
    const int wq0 = wid * 16;
    const int lr = lane & 15, lc = (lane >> 4) * 8;
    const int gr = lane >> 2, gc = (lane & 3) * 2;

    const char* gQ = (const char*)qkvh + ((size_t)(b * SEQ + qb * 128)) * (TDMODEL * 2)
                     + h * 256;
    const char* gK = (const char*)qkvh + ((size_t)(b * SEQ)) * (TDMODEL * 2)
                     + DMODEL * 2 + h * 256;
    const char* gVh = (const char*)vth + ((size_t)((b * NH + h) * HD)) * (SEQ * 2);
    const char* gVl = (const char*)vtl + ((size_t)((b * NH + h) * HD)) * (SEQ * 2);

    {
#pragma unroll
        for (int i = 0; i < 8; i++) {
            int c = tid + i * 256;
            int row = c >> 4, coff = (c & 15) * 16;
            cp16(sb + SM_Q + row * (QSTR * 2) + coff, gQ + (size_t)row * 12288 + coff);
        }
        asm volatile("cp.async.commit_group;" ::: "memory");
    }
    auto load_stage = [&](int kt, int buf) {
        const uint32_t kb_ = sb + SM_K + buf * 17408;
        const uint32_t vb_ = sb + SM_VT + buf * 36864;
#pragma unroll
        for (int i = 0; i < 4; i++) {
            int c = tid + i * 256;
            int row = c >> 4, coff = (c & 15) * 16;
            cp16(kb_ + row * (QSTR * 2) + coff,
                 gK + (size_t)(kt * 64 + row) * 12288 + coff);
        }
#pragma unroll
        for (int i = 0; i < 4; i++) {
            int c = tid + i * 256;
            int row = c >> 3, coff = (c & 7) * 16;
            size_t go = (size_t)row * (SEQ * 2) + (size_t)kt * 128 + coff;
            cp16(vb_ + row * (VTSTR * 2) + coff, gVh + go);
            cp16(vb_ + 18432 + row * (VTSTR * 2) + coff, gVl + go);
        }
        asm volatile("cp.async.commit_group;" ::: "memory");
    };
    load_stage(0, 0);

    uint32_t qf[8][4];
    float acc_o[8][2][4];
#pragma unroll
    for (int gd = 0; gd < 8; gd++)
#pragma unroll
        for (int p = 0; p < 2; p++)
#pragma unroll
            for (int c = 0; c < 4; c++) acc_o[gd][p][c] = 0.f;
    float m0 = MASKV, m1 = MASKV, l0 = 0.f, l1 = 0.f;

    const int ktmax = 2 * qb + 1;
    const int q_row0 = qb * 128 + wq0 + gr;

    for (int kt = 0; kt <= ktmax; kt++) {
        const int buf = kt & 1;
        if (kt < ktmax) {
            load_stage(kt + 1, buf ^ 1);
            asm volatile("cp.async.wait_group 1;" ::: "memory");
        } else {
            asm volatile("cp.async.wait_group 0;" ::: "memory");
        }
        __syncthreads();

        if (kt == 0) {
#pragma unroll
            for (int dc = 0; dc < 8; dc++) {
                uint32_t off = sb + SM_Q + (uint32_t)((wq0 + lr) * QSTR + dc * 16 + lc) * 2;
                ldsm_x4(off, qf[dc][0], qf[dc][1], qf[dc][2], qf[dc][3]);
            }
        }

        const uint32_t kb_ = sb + SM_K + buf * 17408;
        const uint32_t vb_ = sb + SM_VT + buf * 36864;

        float s[4][2][4];
#pragma unroll
        for (int g = 0; g < 4; g++)
#pragma unroll
            for (int p = 0; p < 2; p++)
#pragma unroll
                for (int c = 0; c < 4; c++) s[g][p][c] = 0.f;
#pragma unroll
        for (int dc = 0; dc < 8; dc++)
#pragma unroll
            for (int g = 0; g < 4; g++) {
                uint32_t kbt[4];
                ldsm_x4(kb_ + (uint32_t)((g * 16 + lr) * QSTR + dc * 16 + lc) * 2,
                        kbt[0], kbt[1], kbt[2], kbt[3]);
                mma_bf16(s[g][0], qf[dc], kbt[0], kbt[2]);
                mma_bf16(s[g][1], qf[dc], kbt[1], kbt[3]);
            }

        if (kt >= 2 * qb) {
#pragma unroll
            for (int g = 0; g < 4; g++)
#pragma unroll
                for (int p = 0; p < 2; p++) {
                    int key = kt * 64 + g * 16 + p * 8 + gc;
                    if (key > q_row0)     s[g][p][0] = MASKV;
                    if (key + 1 > q_row0) s[g][p][1] = MASKV;
                    if (key > q_row0 + 8)     s[g][p][2] = MASKV;
                    if (key + 1 > q_row0 + 8) s[g][p][3] = MASKV;
                }
        }

        float t0 = MASKV, t1 = MASKV;
#pragma unroll
        for (int g = 0; g < 4; g++)
#pragma unroll
            for (int p = 0; p < 2; p++) {
                t0 = fmaxf(t0, fmaxf(s[g][p][0], s[g][p][1]));
                t1 = fmaxf(t1, fmaxf(s[g][p][2], s[g][p][3]));
            }
        t0 = fmaxf(t0, __shfl_xor_sync(0xffffffffu, t0, 1));
        t0 = fmaxf(t0, __shfl_xor_sync(0xffffffffu, t0, 2));
        t1 = fmaxf(t1, __shfl_xor_sync(0xffffffffu, t1, 1));
        t1 = fmaxf(t1, __shfl_xor_sync(0xffffffffu, t1, 2));
        float mn0 = fmaxf(m0, t0), mn1 = fmaxf(m1, t1);
        float a0 = ex2f((m0 - mn0) * CEXP), a1 = ex2f((m1 - mn1) * CEXP);
        m0 = mn0; m1 = mn1;

        uint32_t pah[4][4], pal[4][4];
        float sum0 = 0.f, sum1 = 0.f;
#pragma unroll
        for (int g = 0; g < 4; g++)
#pragma unroll
            for (int p = 0; p < 2; p++) {
                float p0 = ex2f((s[g][p][0] - mn0) * CEXP);
                float p1 = ex2f((s[g][p][1] - mn0) * CEXP);
                float p2 = ex2f((s[g][p][2] - mn1) * CEXP);
                float p3 = ex2f((s[g][p][3] - mn1) * CEXP);
                sum0 += p0 + p1; sum1 += p2 + p3;
                pah[g][2 * p]     = pack2bf(p0, p1);
                pah[g][2 * p + 1] = pack2bf(p2, p3);
                pal[g][2 * p]     = pack2bf(p0 - bf_hi_f(p0), p1 - bf_hi_f(p1));
                pal[g][2 * p + 1] = pack2bf(p2 - bf_hi_f(p2), p3 - bf_hi_f(p3));
            }
        sum0 += __shfl_xor_sync(0xffffffffu, sum0, 1);
        sum0 += __shfl_xor_sync(0xffffffffu, sum0, 2);
        sum1 += __shfl_xor_sync(0xffffffffu, sum1, 1);
        sum1 += __shfl_xor_sync(0xffffffffu, sum1, 2);
        l0 = l0 * a0 + sum0;
        l1 = l1 * a1 + sum1;

#pragma unroll
        for (int gd = 0; gd < 8; gd++)
#pragma unroll
            for (int p = 0; p < 2; p++) {
                acc_o[gd][p][0] *= a0; acc_o[gd][p][1] *= a0;
                acc_o[gd][p][2] *= a1; acc_o[gd][p][3] *= a1;
            }

#pragma unroll
        for (int kc = 0; kc < 4; kc++)
#pragma unroll
            for (int gd = 0; gd < 8; gd++) {
                uint32_t off = (uint32_t)((gd * 16 + lr) * VTSTR + kc * 16 + lc) * 2;
                uint32_t bvh[4], bvl[4];
                ldsm_x4(vb_ + off, bvh[0], bvh[1], bvh[2], bvh[3]);
                ldsm_x4(vb_ + 18432 + off, bvl[0], bvl[1], bvl[2], bvl[3]);
                mma_bf16(acc_o[gd][0], pah[kc], bvh[0], bvh[2]);
                mma_bf16(acc_o[gd][1], pah[kc], bvh[1], bvh[3]);
                mma_bf16(acc_o[gd][0], pah[kc], bvl[0], bvl[2]);
                mma_bf16(acc_o[gd][1], pah[kc], bvl[1], bvl[3]);
                mma_bf16(acc_o[gd][0], pal[kc], bvh[0], bvh[2]);
                mma_bf16(acc_o[gd][1], pal[kc], bvh[1], bvh[3]);
            }
        __syncthreads();
    }

    const float i0 = 1.f / l0, i1 = 1.f / l1;
    const size_t tok0 = (size_t)b * SEQ + qb * 128 + wq0 + gr;
#pragma unroll
    for (int gd = 0; gd < 8; gd++)
#pragma unroll
        for (int p = 0; p < 2; p++) {
            int col = h * HD + gd * 16 + p * 8 + gc;
            float v0 = acc_o[gd][p][0] * i0, v1 = acc_o[gd][p][1] * i0;
            float v2 = acc_o[gd][p][2] * i1, v3 = acc_o[gd][p][3] * i1;
            size_t o0 = tok0 * DMODEL + col, o1 = (tok0 + 8) * DMODEL + col;
            *(uint32_t*)&ath[o0] = pack2bf(v0, v1);
            *(uint32_t*)&atl[o0] = pack2bf(v0 - bf_hi_f(v0), v1 - bf_hi_f(v1));
            *(uint32_t*)&ath[o1] = pack2bf(v2, v3);
            *(uint32_t*)&atl[o1] = pack2bf(v2 - bf_hi_f(v2), v3 - bf_hi_f(v3));
        }
}

// ---------------------------------------------------------------------------
extern "C" void kernel_launch(void* const* d_in, const int* in_sizes, int n_in,
                              void* d_out, int out_size)
{
    const float* x    = (const float*)d_in[0];
    const float* Wqkv = (const float*)d_in[1];
    const float* Wo   = (const float*)d_in[2];
    float* out = (float*)d_out;

    void* p;
    cudaGetSymbolAddress(&p, g_xh);    __nv_bfloat16* xh = (__nv_bfloat16*)p;
    cudaGetSymbolAddress(&p, g_xl);    __nv_bfloat16* xl = (__nv_bfloat16*)p;
    cudaGetSymbolAddress(&p, g_wqkvh); __nv_bfloat16* wqh = (__nv_bfloat16*)p;
    cudaGetSymbolAddress(&p, g_wqkvl); __nv_bfloat16* wql = (__nv_bfloat16*)p;
    cudaGetSymbolAddress(&p, g_woh);   __nv_bfloat16* woh = (__nv_bfloat16*)p;
    cudaGetSymbolAddress(&p, g_wol);   __nv_bfloat16* wol = (__nv_bfloat16*)p;
    cudaGetSymbolAddress(&p, g_qkvh);  __nv_bfloat16* qvh = (__nv_bfloat16*)p;
    cudaGetSymbolAddress(&p, g_qkvl);  __nv_bfloat16* qvl = (__nv_bfloat16*)p;
    cudaGetSymbolAddress(&p, g_vth);   __nv_bfloat16* vth = (__nv_bfloat16*)p;
    cudaGetSymbolAddress(&p, g_vtl);   __nv_bfloat16* vtl = (__nv_bfloat16*)p;
    cudaGetSymbolAddress(&p, g_ath);   __nv_bfloat16* ath = (__nv_bfloat16*)p;
    cudaGetSymbolAddress(&p, g_atl);   __nv_bfloat16* atl = (__nv_bfloat16*)p;

    cudaFuncSetAttribute(gemm_mma<true, 1>, cudaFuncAttributeMaxDynamicSharedMemorySize,
                         2 * OPB);
    cudaFuncSetAttribute(gemm_mma<true, 3>, cudaFuncAttributeMaxDynamicSharedMemorySize,
                         4 * OPB);
    cudaFuncSetAttribute(gemm_mma<false, 3>, cudaFuncAttributeMaxDynamicSharedMemorySize,
                         4 * OPB);
    cudaFuncSetAttribute(attn_mma, cudaFuncAttributeMaxDynamicSharedMemorySize,
                         ATTN_SMEM_BYTES);

    // 0) split inputs
    split_kernel<<<(NR * DMODEL / 4 + 255) / 256, 256>>>(x, xh, xl, NR * DMODEL / 4);
    split_kernel<<<(TDMODEL * DMODEL / 4 + 255) / 256, 256>>>(Wqkv, wqh, wql,
                                                              TDMODEL * DMODEL / 4);
    split_kernel<<<(DMODEL * DMODEL / 4 + 255) / 256, 256>>>(Wo, woh, wol,
                                                             DMODEL * DMODEL / 4);

    // 1a) Q,K projection: single-pass bf16 (scores are tiny; error harmless)
    gemm_mma<true, 1><<<dim3(2 * DMODEL / 128, NR / 128), 256, 2 * OPB>>>(
        xh, xl, wqh, wql, nullptr, qvh, qvl, TDMODEL, DMODEL);

    // 1b) V projection: 3-pass split (feeds output linearly; needs accuracy)
    gemm_mma<true, 3><<<dim3(DMODEL / 128, NR / 128), 256, 4 * OPB>>>(
        xh, xl, wqh + (size_t)2 * DMODEL * DMODEL, wql + (size_t)2 * DMODEL * DMODEL,
        nullptr, qvh + 2 * DMODEL, qvl + 2 * DMODEL, TDMODEL, DMODEL);

    // 2) transpose V panels
    vtrans_kernel<<<dim3(SEQ / 32, HD / 32, NB * NH), dim3(32, 8)>>>(
        (const ushort*)qvh, (const ushort*)qvl, (ushort*)vth, (ushort*)vtl);

    // 3) attention -> bf16 hi/lo
    attn_mma<<<dim3(16, NH, NB), 256, ATTN_SMEM_BYTES>>>(qvh, vth, vtl, ath, atl);

    // 4) out = att @ Wo^T (fp32 out, 3-pass)
    gemm_mma<false, 3><<<dim3(DMODEL / 128, NR / 128), 256, 4 * OPB>>>(
        ath, atl, woh, wol, out, nullptr, nullptr, DMODEL, DMODEL);
}

// round 7
// speedup vs baseline: 3.9141x; 1.1268x over previous
#include <cuda_runtime.h>
#include <cuda_bf16.h>
#include <math.h>
#include <stdint.h>

#define DMODEL 2048
#define TDMODEL 6144
#define NR 4096      // B*S rows
#define NH 16
#define HD 128
#define SEQ 2048
#define NB 2

// ---------------------------------------------------------------------------
// Scratch (no allocations allowed)
// ---------------------------------------------------------------------------
__device__ __nv_bfloat16 g_xh[(size_t)NR * DMODEL];
__device__ __nv_bfloat16 g_xl[(size_t)NR * DMODEL];
__device__ __nv_bfloat16 g_wqkvh[(size_t)TDMODEL * DMODEL];
__device__ __nv_bfloat16 g_wqkvl[(size_t)TDMODEL * DMODEL];
__device__ __nv_bfloat16 g_woh[(size_t)DMODEL * DMODEL];
__device__ __nv_bfloat16 g_wol[(size_t)DMODEL * DMODEL];
__device__ __nv_bfloat16 g_qkvh[(size_t)NR * TDMODEL];
__device__ __nv_bfloat16 g_qkvl[(size_t)NR * TDMODEL];
__device__ __nv_bfloat16 g_vth[(size_t)NB * NH * HD * SEQ];   // [b][h][d][tok]
__device__ __nv_bfloat16 g_vtl[(size_t)NB * NH * HD * SEQ];
__device__ __nv_bfloat16 g_ath[(size_t)NR * DMODEL];
__device__ __nv_bfloat16 g_atl[(size_t)NR * DMODEL];

// ---------------------------------------------------------------------------
// PTX helpers (sm_80+ portable)
// ---------------------------------------------------------------------------
__device__ __forceinline__ uint32_t smem_u32(const void* p) {
    uint32_t a;
    asm("{ .reg .u64 t; cvta.to.shared.u64 t, %1; cvt.u32.u64 %0, t; }" : "=r"(a) : "l"(p));
    return a;
}
__device__ __forceinline__ void cp16(uint32_t dst, const void* src) {
    asm volatile("cp.async.cg.shared.global [%0], [%1], 16;" :: "r"(dst), "l"(src));
}
__device__ __forceinline__ void ldsm_x4(uint32_t addr, uint32_t& r0, uint32_t& r1,
                                        uint32_t& r2, uint32_t& r3) {
    asm volatile("ldmatrix.sync.aligned.m8n8.x4.shared.b16 {%0,%1,%2,%3}, [%4];"
                 : "=r"(r0), "=r"(r1), "=r"(r2), "=r"(r3) : "r"(addr));
}
__device__ __forceinline__ void mma_bf16(float* d, const uint32_t* a,
                                         uint32_t b0, uint32_t b1) {
    asm volatile(
        "mma.sync.aligned.m16n8k16.row.col.f32.bf16.bf16.f32 "
        "{%0,%1,%2,%3}, {%4,%5,%6,%7}, {%8,%9}, {%0,%1,%2,%3};"
        : "+f"(d[0]), "+f"(d[1]), "+f"(d[2]), "+f"(d[3])
        : "r"(a[0]), "r"(a[1]), "r"(a[2]), "r"(a[3]), "r"(b0), "r"(b1));
}
__device__ __forceinline__ float ex2f(float x) {
    float y; asm("ex2.approx.f32 %0, %1;" : "=f"(y) : "f"(x)); return y;
}
// pack {lo, hi} fp32 -> bf16x2 (lo in bits [0:16))
__device__ __forceinline__ uint32_t pack2bf(float lo, float hi) {
    uint32_t r;
    asm("cvt.rn.bf16x2.f32 %0, %1, %2;" : "=r"(r) : "f"(hi), "f"(lo));
    return r;
}
__device__ __forceinline__ float bf_hi_f(float v) {
    return __bfloat162float(__float2bfloat16(v));
}
// swizzle for 64 B/row smem tiles: flips chunk bits [4:6) by row bits [7:9)
__device__ __forceinline__ uint32_t swz64(uint32_t o) {
    return o ^ (((o >> 7) & 3u) << 4);
}

// ---------------------------------------------------------------------------
// Split fp32 -> bf16 hi + bf16 lo (residual)
// ---------------------------------------------------------------------------
__global__ void split_kernel(const float* __restrict__ s,
                             __nv_bfloat16* __restrict__ h,
                             __nv_bfloat16* __restrict__ l, int n4)
{
    int i = blockIdx.x * blockDim.x + threadIdx.x;
    if (i >= n4) return;
    float4 v = ((const float4*)s)[i];
    uint2 uh, ul;
    uh.x = pack2bf(v.x, v.y);
    uh.y = pack2bf(v.z, v.w);
    ul.x = pack2bf(v.x - bf_hi_f(v.x), v.y - bf_hi_f(v.y));
    ul.y = pack2bf(v.z - bf_hi_f(v.z), v.w - bf_hi_f(v.w));
    ((uint2*)h)[i] = uh;
    ((uint2*)l)[i] = ul;
}

// ---------------------------------------------------------------------------
// V transpose: qkv[tok][4096 + h*128 + d] -> vt[(b,h)][d][tok]  (bf16 bits)
// ---------------------------------------------------------------------------
__global__ void vtrans_kernel(const ushort* __restrict__ qh, const ushort* __restrict__ ql,
                              ushort* __restrict__ vh, ushort* __restrict__ vl)
{
    __shared__ ushort t0[32][33], t1[32][33];
    const int bh = blockIdx.z, b = bh >> 4, h = bh & 15;
    const int tok0 = blockIdx.x * 32, d0 = blockIdx.y * 32;
    const int tx = threadIdx.x, ty = threadIdx.y;
    const size_t sbase = ((size_t)(b * SEQ + tok0)) * TDMODEL + 2 * DMODEL + h * HD + d0;
#pragma unroll
    for (int i = 0; i < 4; i++) {
        int r = ty + i * 8;
        t0[r][tx] = qh[sbase + (size_t)r * TDMODEL + tx];
        t1[r][tx] = ql[sbase + (size_t)r * TDMODEL + tx];
    }
    __syncthreads();
    const size_t dbase = ((size_t)(bh * HD + d0)) * SEQ + tok0;
#pragma unroll
    for (int i = 0; i < 4; i++) {
        int r = ty + i * 8;
        vh[dbase + (size_t)r * SEQ + tx] = t0[tx][r];
        vl[dbase + (size_t)r * SEQ + tx] = t1[tx][r];
    }
}

// ---------------------------------------------------------------------------
// mma.sync NT GEMM, NPASS = 1 (hi*hi) or 3 (hi*hi + hi*lo + lo*hi).
// 128x128 tile, BK=32, 8 warps (2x4), warp tile 64x32.
// 3-stage cp.async ring, XOR-swizzled smem (no padding), 1 sync per stage.
// ---------------------------------------------------------------------------
#define TS 8192u                         // 128 rows x 64 B per operand stage
#define NSTG 3

template<bool SPLIT, int NPASS>
__global__ __launch_bounds__(256, 2)
void gemm_mma(const __nv_bfloat16* __restrict__ Ah, const __nv_bfloat16* __restrict__ Al,
              const __nv_bfloat16* __restrict__ Bh, const __nv_bfloat16* __restrict__ Bl,
              float* __restrict__ C, __nv_bfloat16* __restrict__ Ch,
              __nv_bfloat16* __restrict__ Cl, int ldc, int K)
{
    extern __shared__ char smem[];
    const uint32_t sb = (smem_u32(smem) + 1023u) & ~1023u;
    const uint32_t sAh = sb;
    const uint32_t sBh = sb + NSTG * TS;
    const uint32_t sAl = sb + 2 * NSTG * TS;       // NPASS==3 only
    const uint32_t sBl = sb + 3 * NSTG * TS;

    const int tid = threadIdx.x, lane = tid & 31, wid = tid >> 5;
    const int bm = blockIdx.y * 128, bn = blockIdx.x * 128;
    const int m0 = (wid & 1) * 64, n0 = (wid >> 1) * 32;

    const char* gAh = (const char*)(Ah + (size_t)bm * K);
    const char* gAl = (const char*)(Al + (size_t)bm * K);
    const char* gBh = (const char*)(Bh + (size_t)bn * K);
    const char* gBl = (const char*)(Bl + (size_t)bn * K);

    float acc[4][4][4];
#pragma unroll
    for (int i = 0; i < 4; i++)
#pragma unroll
        for (int j = 0; j < 4; j++)
#pragma unroll
            for (int c = 0; c < 4; c++) acc[i][j][c] = 0.f;

    const int lrow = tid >> 2;                  // 0..63 (+64 second half)
    const int lch = (tid & 3) * 16;             // chunk byte offset in 64-B row

    auto load_stage = [&](int kb, int buf) {
        const uint32_t bufo = (uint32_t)buf * TS;
#pragma unroll
        for (int t = 0; t < 2; t++) {
            int row = lrow + t * 64;
            uint32_t so = swz64((uint32_t)(row * 64) + lch) + bufo;
            size_t go = ((size_t)row * K + (size_t)kb * 32) * 2 + lch;
            cp16(sAh + so, gAh + go);
            cp16(sBh + so, gBh + go);
            if (NPASS == 3) {
                cp16(sAl + so, gAl + go);
                cp16(sBl + so, gBl + go);
            }
        }
        asm volatile("cp.async.commit_group;" ::: "memory");
    };

    const int nk = K / 32;
    load_stage(0, 0);
    load_stage(1, 1);

    const int lr = lane & 15;
    const int lcb = (lane >> 4) * 16;           // 0 or 16 bytes (8 bf16)

    for (int kb = 0; kb < nk; kb++) {
        const int buf = kb % NSTG;
        asm volatile("cp.async.wait_group %0;" :: "n"(NSTG - 2) : "memory");
        __syncthreads();
        {   // prefetch kb+2 into the ring slot just freed
            int nkb = kb + NSTG - 1;
            if (nkb < nk) load_stage(nkb, nkb % NSTG);
            else asm volatile("cp.async.commit_group;" ::: "memory");
        }
        const uint32_t bufo = (uint32_t)buf * TS;

#pragma unroll
        for (int ks = 0; ks < 2; ks++) {
            uint32_t ah[4][4], al[4][4], bh[2][4], bl[2][4];
#pragma unroll
            for (int mt = 0; mt < 4; mt++) {
                uint32_t off = swz64((uint32_t)((m0 + mt * 16 + lr) * 64 + ks * 32) + lcb)
                               + bufo;
                ldsm_x4(sAh + off, ah[mt][0], ah[mt][1], ah[mt][2], ah[mt][3]);
                if (NPASS == 3)
                    ldsm_x4(sAl + off, al[mt][0], al[mt][1], al[mt][2], al[mt][3]);
            }
#pragma unroll
            for (int g = 0; g < 2; g++) {
                uint32_t off = swz64((uint32_t)((n0 + g * 16 + lr) * 64 + ks * 32) + lcb)
                               + bufo;
                ldsm_x4(sBh + off, bh[g][0], bh[g][1], bh[g][2], bh[g][3]);
                if (NPASS == 3)
                    ldsm_x4(sBl + off, bl[g][0], bl[g][1], bl[g][2], bl[g][3]);
            }
#pragma unroll
            for (int mt = 0; mt < 4; mt++)
#pragma unroll
                for (int nt = 0; nt < 4; nt++) {
                    const int g = nt >> 1, p = nt & 1;
                    mma_bf16(acc[mt][nt], ah[mt], bh[g][p], bh[g][p + 2]);
                    if (NPASS == 3) {
                        mma_bf16(acc[mt][nt], ah[mt], bl[g][p], bl[g][p + 2]);
                        mma_bf16(acc[mt][nt], al[mt], bh[g][p], bh[g][p + 2]);
                    }
                }
        }
    }

    const int gr = lane >> 2, gc = (lane & 3) * 2;
#pragma unroll
    for (int mt = 0; mt < 4; mt++)
#pragma unroll
        for (int nt = 0; nt < 4; nt++) {
            int r = bm + m0 + mt * 16 + gr;
            int cix = bn + n0 + nt * 8 + gc;
            if (SPLIT) {
#pragma unroll
                for (int half = 0; half < 2; half++) {
                    float v0 = acc[mt][nt][half * 2], v1 = acc[mt][nt][half * 2 + 1];
                    size_t o = (size_t)(r + half * 8) * ldc + cix;
                    *(uint32_t*)&Ch[o] = pack2bf(v0, v1);
                    *(uint32_t*)&Cl[o] = pack2bf(v0 - bf_hi_f(v0), v1 - bf_hi_f(v1));
                }
            } else {
                *(float2*)&C[(size_t)r * ldc + cix] =
                    make_float2(acc[mt][nt][0], acc[mt][nt][1]);
                *(float2*)&C[(size_t)(r + 8) * ldc + cix] =
                    make_float2(acc[mt][nt][2], acc[mt][nt][3]);
            }
        }
}

#define GEMM1_SMEM (2 * NSTG * TS + 1024)      // 50176
#define GEMM3_SMEM (4 * NSTG * TS + 1024)      // 99328

// ---------------------------------------------------------------------------
// Tensor-core causal flash attention (unchanged from R6).
// ---------------------------------------------------------------------------
#define QSTR 136
#define VTSTR 72
#define SM_Q 0
#define SM_K 34816
#define SM_VT 69632
#define ATTN_SMEM_BYTES 143360
#define CEXP 0.12751744f                 // log2(e)/sqrt(128)
#define MASKV (-1e30f)

__global__ __launch_bounds__(256, 1)
void attn_mma(const __nv_bfloat16* __restrict__ qkvh,
              const __nv_bfloat16* __restrict__ vth,
              const __nv_bfloat16* __restrict__ vtl,
              __nv_bfloat16* __restrict__ ath, __nv_bfloat16* __restrict__ atl)
{
    extern __shared__ char smem[];
    const uint32_t sb = smem_u32(smem);

    const int tid = threadIdx.x, lane = tid & 31, wid = tid >> 5;
    const int qb = 15 - blockIdx.x;
    const int h = blockIdx.y, b = blockIdx.z;
    const int wq0 = wid * 16;
    const int lr = lane & 15, lc = (lane >> 4) * 8;
    const int gr = lane >> 2, gc = (lane & 3) * 2;

    const char* gQ = (const char*)qkvh + ((size_t)(b * SEQ + qb * 128)) * (TDMODEL * 2)
                     + h * 256;
    const char* gK = (const char*)qkvh + ((size_t)(b * SEQ)) * (TDMODEL * 2)
                     + DMODEL * 2 + h * 256;
    const char* gVh = (const char*)vth + ((size_t)((b * NH + h) * HD)) * (SEQ * 2);
    const char* gVl = (const char*)vtl + ((size_t)((b * NH + h) * HD)) * (SEQ * 2);

    {
#pragma unroll
        for (int i = 0; i < 8; i++) {
            int c = tid + i * 256;
            int row = c >> 4, coff = (c & 15) * 16;
            cp16(sb + SM_Q + row * (QSTR * 2) + coff, gQ + (size_t)row * 12288 + coff);
        }
        asm volatile("cp.async.commit_group;" ::: "memory");
    }
    auto load_stage = [&](int kt, int buf) {
        const uint32_t kb_ = sb + SM_K + buf * 17408;
        const uint32_t vb_ = sb + SM_VT + buf * 36864;
#pragma unroll
        for (int i = 0; i < 4; i++) {
            int c = tid + i * 256;
            int row = c >> 4, coff = (c & 15) * 16;
            cp16(kb_ + row * (QSTR * 2) + coff,
                 gK + (size_t)(kt * 64 + row) * 12288 + coff);
        }
#pragma unroll
        for (int i = 0; i < 4; i++) {
            int c = tid + i * 256;
            int row = c >> 3, coff = (c & 7) * 16;
            size_t go = (size_t)row * (SEQ * 2) + (size_t)kt * 128 + coff;
            cp16(vb_ + row * (VTSTR * 2) + coff, gVh + go);
            cp16(vb_ + 18432 + row * (VTSTR * 2) + coff, gVl + go);
        }
        asm volatile("cp.async.commit_group;" ::: "memory");
    };
    load_stage(0, 0);

    uint32_t qf[8][4];
    float acc_o[8][2][4];
#pragma unroll
    for (int gd = 0; gd < 8; gd++)
#pragma unroll
        for (int p = 0; p < 2; p++)
#pragma unroll
            for (int c = 0; c < 4; c++) acc_o[gd][p][c] = 0.f;
    float m0 = MASKV, m1 = MASKV, l0 = 0.f, l1 = 0.f;

    const int ktmax = 2 * qb + 1;
    const int q_row0 = qb * 128 + wq0 + gr;

    for (int kt = 0; kt <= ktmax; kt++) {
        const int buf = kt & 1;
        if (kt < ktmax) {
            load_stage(kt + 1, buf ^ 1);
            asm volatile("cp.async.wait_group 1;" ::: "memory");
        } else {
            asm volatile("cp.async.wait_group 0;" ::: "memory");
        }
        __syncthreads();

        if (kt == 0) {
#pragma unroll
            for (int dc = 0; dc < 8; dc++) {
                uint32_t off = sb + SM_Q + (uint32_t)((wq0 + lr) * QSTR + dc * 16 + lc) * 2;
                ldsm_x4(off, qf[dc][0], qf[dc][1], qf[dc][2], qf[dc][3]);
            }
        }

        const uint32_t kb_ = sb + SM_K + buf * 17408;
        const uint32_t vb_ = sb + SM_VT + buf * 36864;

        float s[4][2][4];
#pragma unroll
        for (int g = 0; g < 4; g++)
#pragma unroll
            for (int p = 0; p < 2; p++)
#pragma unroll
                for (int c = 0; c < 4; c++) s[g][p][c] = 0.f;
#pragma unroll
        for (int dc = 0; dc < 8; dc++)
#pragma unroll
            for (int g = 0; g < 4; g++) {
                uint32_t kbt[4];
                ldsm_x4(kb_ + (uint32_t)((g * 16 + lr) * QSTR + dc * 16 + lc) * 2,
                        kbt[0], kbt[1], kbt[2], kbt[3]);
                mma_bf16(s[g][0], qf[dc], kbt[0], kbt[2]);
                mma_bf16(s[g][1], qf[dc], kbt[1], kbt[3]);
            }

        if (kt >= 2 * qb) {
#pragma unroll
            for (int g = 0; g < 4; g++)
#pragma unroll
                for (int p = 0; p < 2; p++) {
                    int key = kt * 64 + g * 16 + p * 8 + gc;
                    if (key > q_row0)     s[g][p][0] = MASKV;
                    if (key + 1 > q_row0) s[g][p][1] = MASKV;
                    if (key > q_row0 + 8)     s[g][p][2] = MASKV;
                    if (key + 1 > q_row0 + 8) s[g][p][3] = MASKV;
                }
        }

        float t0 = MASKV, t1 = MASKV;
#pragma unroll
        for (int g = 0; g < 4; g++)
#pragma unroll
            for (int p = 0; p < 2; p++) {
                t0 = fmaxf(t0, fmaxf(s[g][p][0], s[g][p][1]));
                t1 = fmaxf(t1, fmaxf(s[g][p][2], s[g][p][3]));
            }
        t0 = fmaxf(t0, __shfl_xor_sync(0xffffffffu, t0, 1));
        t0 = fmaxf(t0, __shfl_xor_sync(0xffffffffu, t0, 2));
        t1 = fmaxf(t1, __shfl_xor_sync(0xffffffffu, t1, 1));
        t1 = fmaxf(t1, __shfl_xor_sync(0xffffffffu, t1, 2));
        float mn0 = fmaxf(m0, t0), mn1 = fmaxf(m1, t1);
        float a0 = ex2f((m0 - mn0) * CEXP), a1 = ex2f((m1 - mn1) * CEXP);
        m0 = mn0; m1 = mn1;

        uint32_t pah[4][4], pal[4][4];
        float sum0 = 0.f, sum1 = 0.f;
#pragma unroll
        for (int g = 0; g < 4; g++)
#pragma unroll
            for (int p = 0; p < 2; p++) {
                float p0 = ex2f((s[g][p][0] - mn0) * CEXP);
                float p1 = ex2f((s[g][p][1] - mn0) * CEXP);
                float p2 = ex2f((s[g][p][2] - mn1) * CEXP);
                float p3 = ex2f((s[g][p][3] - mn1) * CEXP);
                sum0 += p0 + p1; sum1 += p2 + p3;
                pah[g][2 * p]     = pack2bf(p0, p1);
                pah[g][2 * p + 1] = pack2bf(p2, p3);
                pal[g][2 * p]     = pack2bf(p0 - bf_hi_f(p0), p1 - bf_hi_f(p1));
                pal[g][2 * p + 1] = pack2bf(p2 - bf_hi_f(p2), p3 - bf_hi_f(p3));
            }
        sum0 += __shfl_xor_sync(0xffffffffu, sum0, 1);
        sum0 += __shfl_xor_sync(0xffffffffu, sum0, 2);
        sum1 += __shfl_xor_sync(0xffffffffu, sum1, 1);
        sum1 += __shfl_xor_sync(0xffffffffu, sum1, 2);
        l0 = l0 * a0 + sum0;
        l1 = l1 * a1 + sum1;

#pragma unroll
        for (int gd = 0; gd < 8; gd++)
#pragma unroll
            for (int p = 0; p < 2; p++) {
                acc_o[gd][p][0] *= a0; acc_o[gd][p][1] *= a0;
                acc_o[gd][p][2] *= a1; acc_o[gd][p][3] *= a1;
            }

#pragma unroll
        for (int kc = 0; kc < 4; kc++)
#pragma unroll
            for (int gd = 0; gd < 8; gd++) {
                uint32_t off = (uint32_t)((gd * 16 + lr) * VTSTR + kc * 16 + lc) * 2;
                uint32_t bvh[4], bvl[4];
                ldsm_x4(vb_ + off, bvh[0], bvh[1], bvh[2], bvh[3]);
                ldsm_x4(vb_ + 18432 + off, bvl[0], bvl[1], bvl[2], bvl[3]);
                mma_bf16(acc_o[gd][0], pah[kc], bvh[0], bvh[2]);
                mma_bf16(acc_o[gd][1], pah[kc], bvh[1], bvh[3]);
                mma_bf16(acc_o[gd][0], pah[kc], bvl[0], bvl[2]);
                mma_bf16(acc_o[gd][1], pah[kc], bvl[1], bvl[3]);
                mma_bf16(acc_o[gd][0], pal[kc], bvh[0], bvh[2]);
                mma_bf16(acc_o[gd][1], pal[kc], bvh[1], bvh[3]);
            }
        __syncthreads();
    }

    const float i0 = 1.f / l0, i1 = 1.f / l1;
    const size_t tok0 = (size_t)b * SEQ + qb * 128 + wq0 + gr;
#pragma unroll
    for (int gd = 0; gd < 8; gd++)
#pragma unroll
        for (int p = 0; p < 2; p++) {
            int col = h * HD + gd * 16 + p * 8 + gc;
            float v0 = acc_o[gd][p][0] * i0, v1 = acc_o[gd][p][1] * i0;
            float v2 = acc_o[gd][p][2] * i1, v3 = acc_o[gd][p][3] * i1;
            size_t o0 = tok0 * DMODEL + col, o1 = (tok0 + 8) * DMODEL + col;
            *(uint32_t*)&ath[o0] = pack2bf(v0, v1);
            *(uint32_t*)&atl[o0] = pack2bf(v0 - bf_hi_f(v0), v1 - bf_hi_f(v1));
            *(uint32_t*)&ath[o1] = pack2bf(v2, v3);
            *(uint32_t*)&atl[o1] = pack2bf(v2 - bf_hi_f(v2), v3 - bf_hi_f(v3));
        }
}

// ---------------------------------------------------------------------------
extern "C" void kernel_launch(void* const* d_in, const int* in_sizes, int n_in,
                              void* d_out, int out_size)
{
    const float* x    = (const float*)d_in[0];
    const float* Wqkv = (const float*)d_in[1];
    const float* Wo   = (const float*)d_in[2];
    float* out = (float*)d_out;

    void* p;
    cudaGetSymbolAddress(&p, g_xh);    __nv_bfloat16* xh = (__nv_bfloat16*)p;
    cudaGetSymbolAddress(&p, g_xl);    __nv_bfloat16* xl = (__nv_bfloat16*)p;
    cudaGetSymbolAddress(&p, g_wqkvh); __nv_bfloat16* wqh = (__nv_bfloat16*)p;
    cudaGetSymbolAddress(&p, g_wqkvl); __nv_bfloat16* wql = (__nv_bfloat16*)p;
    cudaGetSymbolAddress(&p, g_woh);   __nv_bfloat16* woh = (__nv_bfloat16*)p;
    cudaGetSymbolAddress(&p, g_wol);   __nv_bfloat16* wol = (__nv_bfloat16*)p;
    cudaGetSymbolAddress(&p, g_qkvh);  __nv_bfloat16* qvh = (__nv_bfloat16*)p;
    cudaGetSymbolAddress(&p, g_qkvl);  __nv_bfloat16* qvl = (__nv_bfloat16*)p;
    cudaGetSymbolAddress(&p, g_vth);   __nv_bfloat16* vth = (__nv_bfloat16*)p;
    cudaGetSymbolAddress(&p, g_vtl);   __nv_bfloat16* vtl = (__nv_bfloat16*)p;
    cudaGetSymbolAddress(&p, g_ath);   __nv_bfloat16* ath = (__nv_bfloat16*)p;
    cudaGetSymbolAddress(&p, g_atl);   __nv_bfloat16* atl = (__nv_bfloat16*)p;

    cudaFuncSetAttribute(gemm_mma<true, 1>, cudaFuncAttributeMaxDynamicSharedMemorySize,
                         GEMM1_SMEM);
    cudaFuncSetAttribute(gemm_mma<true, 3>, cudaFuncAttributeMaxDynamicSharedMemorySize,
                         GEMM3_SMEM);
    cudaFuncSetAttribute(gemm_mma<false, 3>, cudaFuncAttributeMaxDynamicSharedMemorySize,
                         GEMM3_SMEM);
    cudaFuncSetAttribute(attn_mma, cudaFuncAttributeMaxDynamicSharedMemorySize,
                         ATTN_SMEM_BYTES);

    // 0) split inputs
    split_kernel<<<(NR * DMODEL / 4 + 255) / 256, 256>>>(x, xh, xl, NR * DMODEL / 4);
    split_kernel<<<(TDMODEL * DMODEL / 4 + 255) / 256, 256>>>(Wqkv, wqh, wql,
                                                              TDMODEL * DMODEL / 4);
    split_kernel<<<(DMODEL * DMODEL / 4 + 255) / 256, 256>>>(Wo, woh, wol,
                                                             DMODEL * DMODEL / 4);

    // 1a) Q,K projection: single-pass bf16
    gemm_mma<true, 1><<<dim3(2 * DMODEL / 128, NR / 128), 256, GEMM1_SMEM>>>(
        xh, xl, wqh, wql, nullptr, qvh, qvl, TDMODEL, DMODEL);

    // 1b) V projection: 3-pass split
    gemm_mma<true, 3><<<dim3(DMODEL / 128, NR / 128), 256, GEMM3_SMEM>>>(
        xh, xl, wqh + (size_t)2 * DMODEL * DMODEL, wql + (size_t)2 * DMODEL * DMODEL,
        nullptr, qvh + 2 * DMODEL, qvl + 2 * DMODEL, TDMODEL, DMODEL);

    // 2) transpose V panels
    vtrans_kernel<<<dim3(SEQ / 32, HD / 32, NB * NH), dim3(32, 8)>>>(
        (const ushort*)qvh, (const ushort*)qvl, (ushort*)vth, (ushort*)vtl);

    // 3) attention -> bf16 hi/lo
    attn_mma<<<dim3(16, NH, NB), 256, ATTN_SMEM_BYTES>>>(qvh, vth, vtl, ath, atl);

    // 4) out = att @ Wo^T (fp32 out, 3-pass)
    gemm_mma<false, 3><<<dim3(DMODEL / 128, NR / 128), 256, GEMM3_SMEM>>>(
        ath, atl, woh, wol, out, nullptr, nullptr, DMODEL, DMODEL);
}

// round 8
// speedup vs baseline: 3.9277x; 1.0035x over previous
#include <cuda_runtime.h>
#include <cuda_bf16.h>
#include <math.h>
#include <stdint.h>

#define DMODEL 2048
#define TDMODEL 6144
#define NR 4096      // B*S rows
#define NH 16
#define HD 128
#define SEQ 2048
#define NB 2

// ---------------------------------------------------------------------------
// Scratch (no allocations allowed)
// ---------------------------------------------------------------------------
__device__ __nv_bfloat16 g_xh[(size_t)NR * DMODEL];
__device__ __nv_bfloat16 g_xl[(size_t)NR * DMODEL];
__device__ __nv_bfloat16 g_wqkvh[(size_t)TDMODEL * DMODEL];
__device__ __nv_bfloat16 g_wqkvl[(size_t)TDMODEL * DMODEL];
__device__ __nv_bfloat16 g_woh[(size_t)DMODEL * DMODEL];
__device__ __nv_bfloat16 g_wol[(size_t)DMODEL * DMODEL];
__device__ __nv_bfloat16 g_qkvh[(size_t)NR * TDMODEL];
__device__ __nv_bfloat16 g_qkvl[(size_t)NR * TDMODEL];
__device__ __nv_bfloat16 g_vth[(size_t)NB * NH * HD * SEQ];   // [b][h][d][tok]
__device__ __nv_bfloat16 g_vtl[(size_t)NB * NH * HD * SEQ];
__device__ __nv_bfloat16 g_ath[(size_t)NR * DMODEL];
__device__ __nv_bfloat16 g_atl[(size_t)NR * DMODEL];

// ---------------------------------------------------------------------------
// PTX helpers (sm_80+ portable)
// ---------------------------------------------------------------------------
__device__ __forceinline__ uint32_t smem_u32(const void* p) {
    uint32_t a;
    asm("{ .reg .u64 t; cvta.to.shared.u64 t, %1; cvt.u32.u64 %0, t; }" : "=r"(a) : "l"(p));
    return a;
}
__device__ __forceinline__ void cp16(uint32_t dst, const void* src) {
    asm volatile("cp.async.cg.shared.global [%0], [%1], 16;" :: "r"(dst), "l"(src));
}
__device__ __forceinline__ void ldsm_x4(uint32_t addr, uint32_t& r0, uint32_t& r1,
                                        uint32_t& r2, uint32_t& r3) {
    asm volatile("ldmatrix.sync.aligned.m8n8.x4.shared.b16 {%0,%1,%2,%3}, [%4];"
                 : "=r"(r0), "=r"(r1), "=r"(r2), "=r"(r3) : "r"(addr));
}
__device__ __forceinline__ void mma_bf16(float* d, const uint32_t* a,
                                         uint32_t b0, uint32_t b1) {
    asm volatile(
        "mma.sync.aligned.m16n8k16.row.col.f32.bf16.bf16.f32 "
        "{%0,%1,%2,%3}, {%4,%5,%6,%7}, {%8,%9}, {%0,%1,%2,%3};"
        : "+f"(d[0]), "+f"(d[1]), "+f"(d[2]), "+f"(d[3])
        : "r"(a[0]), "r"(a[1]), "r"(a[2]), "r"(a[3]), "r"(b0), "r"(b1));
}
__device__ __forceinline__ float ex2f(float x) {
    float y; asm("ex2.approx.f32 %0, %1;" : "=f"(y) : "f"(x)); return y;
}
// pack {lo, hi} fp32 -> bf16x2 (lo in bits [0:16))
__device__ __forceinline__ uint32_t pack2bf(float lo, float hi) {
    uint32_t r;
    asm("cvt.rn.bf16x2.f32 %0, %1, %2;" : "=r"(r) : "f"(hi), "f"(lo));
    return r;
}
__device__ __forceinline__ float bf_hi_f(float v) {
    return __bfloat162float(__float2bfloat16(v));
}
// swizzle for 64 B/row smem tiles: flips chunk bits [4:6) by row bits [7:9)
__device__ __forceinline__ uint32_t swz64(uint32_t o) {
    return o ^ (((o >> 7) & 3u) << 4);
}

// ---------------------------------------------------------------------------
// Split fp32 -> bf16 hi + bf16 lo (residual)
// ---------------------------------------------------------------------------
__global__ void split_kernel(const float* __restrict__ s,
                             __nv_bfloat16* __restrict__ h,
                             __nv_bfloat16* __restrict__ l, int n4)
{
    int i = blockIdx.x * blockDim.x + threadIdx.x;
    if (i >= n4) return;
    float4 v = ((const float4*)s)[i];
    uint2 uh, ul;
    uh.x = pack2bf(v.x, v.y);
    uh.y = pack2bf(v.z, v.w);
    ul.x = pack2bf(v.x - bf_hi_f(v.x), v.y - bf_hi_f(v.y));
    ul.y = pack2bf(v.z - bf_hi_f(v.z), v.w - bf_hi_f(v.w));
    ((uint2*)h)[i] = uh;
    ((uint2*)l)[i] = ul;
}

// ---------------------------------------------------------------------------
// V transpose: qkv[tok][4096 + h*128 + d] -> vt[(b,h)][d][tok]  (bf16 bits)
// ---------------------------------------------------------------------------
__global__ void vtrans_kernel(const ushort* __restrict__ qh, const ushort* __restrict__ ql,
                              ushort* __restrict__ vh, ushort* __restrict__ vl)
{
    __shared__ ushort t0[32][33], t1[32][33];
    const int bh = blockIdx.z, b = bh >> 4, h = bh & 15;
    const int tok0 = blockIdx.x * 32, d0 = blockIdx.y * 32;
    const int tx = threadIdx.x, ty = threadIdx.y;
    const size_t sbase = ((size_t)(b * SEQ + tok0)) * TDMODEL + 2 * DMODEL + h * HD + d0;
#pragma unroll
    for (int i = 0; i < 4; i++) {
        int r = ty + i * 8;
        t0[r][tx] = qh[sbase + (size_t)r * TDMODEL + tx];
        t1[r][tx] = ql[sbase + (size_t)r * TDMODEL + tx];
    }
    __syncthreads();
    const size_t dbase = ((size_t)(bh * HD + d0)) * SEQ + tok0;
#pragma unroll
    for (int i = 0; i < 4; i++) {
        int r = ty + i * 8;
        vh[dbase + (size_t)r * SEQ + tx] = t0[tx][r];
        vl[dbase + (size_t)r * SEQ + tx] = t1[tx][r];
    }
}

// ---------------------------------------------------------------------------
// mma.sync NT GEMM, NPASS = 1 (hi*hi) or 3 (hi*hi + hi*lo + lo*hi).
// 128x128 tile, BK=32, 8 warps (2x4), warp tile 64x32.
// 3-stage cp.async ring unrolled by 3 (stage offsets compile-time const);
// all ldsm/cp smem addresses precomputed outside the k-loop.
// ---------------------------------------------------------------------------
#define TS 8192u                         // 128 rows x 64 B per operand stage
#define NSTG 3
#define ALOFF (2u * NSTG * TS)           // hi -> lo operand base distance

template<bool SPLIT, int NPASS>
__global__ __launch_bounds__(256, 2)
void gemm_mma(const __nv_bfloat16* __restrict__ Ah, const __nv_bfloat16* __restrict__ Al,
              const __nv_bfloat16* __restrict__ Bh, const __nv_bfloat16* __restrict__ Bl,
              float* __restrict__ C, __nv_bfloat16* __restrict__ Ch,
              __nv_bfloat16* __restrict__ Cl, int ldc, int K)
{
    extern __shared__ char smem[];
    const uint32_t sb = (smem_u32(smem) + 1023u) & ~1023u;
    const uint32_t sAh = sb;
    const uint32_t sBh = sb + NSTG * TS;

    const int tid = threadIdx.x, lane = tid & 31, wid = tid >> 5;
    const int bm = blockIdx.y * 128, bn = blockIdx.x * 128;
    const int m0 = (wid & 1) * 64, n0 = (wid >> 1) * 32;

    const char* gAh = (const char*)(Ah + (size_t)bm * K);
    const char* gAl = (const char*)(Al + (size_t)bm * K);
    const char* gBh = (const char*)(Bh + (size_t)bn * K);
    const char* gBl = (const char*)(Bl + (size_t)bn * K);

    float acc[4][4][4];
#pragma unroll
    for (int i = 0; i < 4; i++)
#pragma unroll
        for (int j = 0; j < 4; j++)
#pragma unroll
            for (int c = 0; c < 4; c++) acc[i][j][c] = 0.f;

    // ---- precomputed cp.async smem offsets (relative to operand base) ----
    const int lrow = tid >> 2;
    const int lch = (tid & 3) * 16;
    uint32_t cpRel[2];
#pragma unroll
    for (int t = 0; t < 2; t++)
        cpRel[t] = swz64((uint32_t)((lrow + t * 64) * 64) + lch);
    uint32_t goRow[2];
#pragma unroll
    for (int t = 0; t < 2; t++) goRow[t] = (uint32_t)((lrow + t * 64) * K * 2) + lch;

    // ---- precomputed ldsm smem addresses (absolute, stage 0) ----
    const int lr = lane & 15;
    const uint32_t lcb = (uint32_t)((lane >> 4) * 16);
    uint32_t aAddr[4][2], bAddr[2][2];
#pragma unroll
    for (int mt = 0; mt < 4; mt++) {
        uint32_t row = (uint32_t)(m0 + mt * 16 + lr);
        uint32_t swz = ((row >> 1) & 3u) << 4;
#pragma unroll
        for (int ks = 0; ks < 2; ks++)
            aAddr[mt][ks] = sAh + row * 64 + (((uint32_t)(ks * 32) | lcb) ^ swz);
    }
#pragma unroll
    for (int g = 0; g < 2; g++) {
        uint32_t row = (uint32_t)(n0 + g * 16 + lr);
        uint32_t swz = ((row >> 1) & 3u) << 4;
#pragma unroll
        for (int ks = 0; ks < 2; ks++)
            bAddr[g][ks] = sBh + row * 64 + (((uint32_t)(ks * 32) | lcb) ^ swz);
    }

    auto load_stage = [&](int kb, uint32_t bufo) {
        const uint32_t gofs = (uint32_t)kb * 64;
#pragma unroll
        for (int t = 0; t < 2; t++) {
            uint32_t so = cpRel[t] + bufo;
            uint32_t go = goRow[t] + gofs;
            cp16(sAh + so, gAh + go);
            cp16(sBh + so, gBh + go);
            if (NPASS == 3) {
                cp16(sAh + ALOFF + so, gAl + go);
                cp16(sBh + ALOFF + so, gBl + go);
            }
        }
        asm volatile("cp.async.commit_group;" ::: "memory");
    };

    const int nk = K / 32;
    load_stage(0, 0);
    load_stage(1, TS);

    for (int kb0 = 0; kb0 < nk; kb0 += NSTG) {
#pragma unroll
        for (int u = 0; u < NSTG; u++) {
            const int kb = kb0 + u;
            if (kb >= nk) break;
            asm volatile("cp.async.wait_group %0;" :: "n"(NSTG - 2) : "memory");
            __syncthreads();
            {
                int nkb = kb + NSTG - 1;
                const uint32_t nbufo = (uint32_t)((u + NSTG - 1) % NSTG) * TS;
                if (nkb < nk) load_stage(nkb, nbufo);
                else asm volatile("cp.async.commit_group;" ::: "memory");
            }
            const uint32_t bufo = (uint32_t)u * TS;

#pragma unroll
            for (int ks = 0; ks < 2; ks++) {
                uint32_t ah[4][4], al[4][4], bh[2][4], bl[2][4];
#pragma unroll
                for (int mt = 0; mt < 4; mt++) {
                    uint32_t addr = aAddr[mt][ks] + bufo;
                    ldsm_x4(addr, ah[mt][0], ah[mt][1], ah[mt][2], ah[mt][3]);
                    if (NPASS == 3)
                        ldsm_x4(addr + ALOFF, al[mt][0], al[mt][1], al[mt][2], al[mt][3]);
                }
#pragma unroll
                for (int g = 0; g < 2; g++) {
                    uint32_t addr = bAddr[g][ks] + bufo;
                    ldsm_x4(addr, bh[g][0], bh[g][1], bh[g][2], bh[g][3]);
                    if (NPASS == 3)
                        ldsm_x4(addr + ALOFF, bl[g][0], bl[g][1], bl[g][2], bl[g][3]);
                }
#pragma unroll
                for (int mt = 0; mt < 4; mt++)
#pragma unroll
                    for (int nt = 0; nt < 4; nt++) {
                        const int g = nt >> 1, p = nt & 1;
                        mma_bf16(acc[mt][nt], ah[mt], bh[g][p], bh[g][p + 2]);
                        if (NPASS == 3) {
                            mma_bf16(acc[mt][nt], ah[mt], bl[g][p], bl[g][p + 2]);
                            mma_bf16(acc[mt][nt], al[mt], bh[g][p], bh[g][p + 2]);
                        }
                    }
            }
        }
    }

    const int gr = lane >> 2, gc = (lane & 3) * 2;
#pragma unroll
    for (int mt = 0; mt < 4; mt++)
#pragma unroll
        for (int nt = 0; nt < 4; nt++) {
            int r = bm + m0 + mt * 16 + gr;
            int cix = bn + n0 + nt * 8 + gc;
            if (SPLIT) {
#pragma unroll
                for (int half = 0; half < 2; half++) {
                    float v0 = acc[mt][nt][half * 2], v1 = acc[mt][nt][half * 2 + 1];
                    size_t o = (size_t)(r + half * 8) * ldc + cix;
                    *(uint32_t*)&Ch[o] = pack2bf(v0, v1);
                    *(uint32_t*)&Cl[o] = pack2bf(v0 - bf_hi_f(v0), v1 - bf_hi_f(v1));
                }
            } else {
                *(float2*)&C[(size_t)r * ldc + cix] =
                    make_float2(acc[mt][nt][0], acc[mt][nt][1]);
                *(float2*)&C[(size_t)(r + 8) * ldc + cix] =
                    make_float2(acc[mt][nt][2], acc[mt][nt][3]);
            }
        }
}

#define GEMM1_SMEM (2 * NSTG * TS + 1024)      // 50176
#define GEMM3_SMEM (4 * NSTG * TS + 1024)      // 99328

// ---------------------------------------------------------------------------
// Tensor-core causal flash attention (unchanged from R7).
// ---------------------------------------------------------------------------
#define QSTR 136
#define VTSTR 72
#define SM_Q 0
#define SM_K 34816
#define SM_VT 69632
#define ATTN_SMEM_BYTES 143360
#define CEXP 0.12751744f                 // log2(e)/sqrt(128)
#define MASKV (-1e30f)

__global__ __launch_bounds__(256, 1)
void attn_mma(const __nv_bfloat16* __restrict__ qkvh,
              const __nv_bfloat16* __restrict__ vth,
              const __nv_bfloat16* __restrict__ vtl,
              __nv_bfloat16* __restrict__ ath, __nv_bfloat16* __restrict__ atl)
{
    extern __shared__ char smem[];
    const uint32_t sb = smem_u32(smem);

    const int tid = threadIdx.x, lane = tid & 31, wid = tid >> 5;
    const int qb = 15 - blockIdx.x;
    const int h = blockIdx.y, b = blockIdx.z;
    const int wq0 = wid * 16;
    const int lr = lane & 15, lc = (lane >> 4) * 8;
    const int gr = lane >> 2, gc = (lane & 3) * 2;

    const char* gQ = (const char*)qkvh + ((size_t)(b * SEQ + qb * 128)) * (TDMODEL * 2)
                     + h * 256;
    const char* gK = (const char*)qkvh + ((size_t)(b * SEQ)) * (TDMODEL * 2)
                     + DMODEL * 2 + h * 256;
    const char* gVh = (const char*)vth + ((size_t)((b * NH + h) * HD)) * (SEQ * 2);
    const char* gVl = (const char*)vtl + ((size_t)((b * NH + h) * HD)) * (SEQ * 2);

    {
#pragma unroll
        for (int i = 0; i < 8; i++) {
            int c = tid + i * 256;
            int row = c >> 4, coff = (c & 15) * 16;
            cp16(sb + SM_Q + row * (QSTR * 2) + coff, gQ + (size_t)row * 12288 + coff);
        }
        asm volatile("cp.async.commit_group;" ::: "memory");
    }
    auto load_stage = [&](int kt, int buf) {
        const uint32_t kb_ = sb + SM_K + buf * 17408;
        const uint32_t vb_ = sb + SM_VT + buf * 36864;
#pragma unroll
        for (int i = 0; i < 4; i++) {
            int c = tid + i * 256;
            int row = c >> 4, coff = (c & 15) * 16;
            cp16(kb_ + row * (QSTR * 2) + coff,
                 gK + (size_t)(kt * 64 + row) * 12288 + coff);
        }
#pragma unroll
        for (int i = 0; i < 4; i++) {
            int c = tid + i * 256;
            int row = c >> 3, coff = (c & 7) * 16;
            size_t go = (size_t)row * (SEQ * 2) + (size_t)kt * 128 + coff;
            cp16(vb_ + row * (VTSTR * 2) + coff, gVh + go);
            cp16(vb_ + 18432 + row * (VTSTR * 2) + coff, gVl + go);
        }
        asm volatile("cp.async.commit_group;" ::: "memory");
    };
    load_stage(0, 0);

    uint32_t qf[8][4];
    float acc_o[8][2][4];
#pragma unroll
    for (int gd = 0; gd < 8; gd++)
#pragma unroll
        for (int p = 0; p < 2; p++)
#pragma unroll
            for (int c = 0; c < 4; c++) acc_o[gd][p][c] = 0.f;
    float m0 = MASKV, m1 = MASKV, l0 = 0.f, l1 = 0.f;

    const int ktmax = 2 * qb + 1;
    const int q_row0 = qb * 128 + wq0 + gr;

    for (int kt = 0; kt <= ktmax; kt++) {
        const int buf = kt & 1;
        if (kt < ktmax) {
            load_stage(kt + 1, buf ^ 1);
            asm volatile("cp.async.wait_group 1;" ::: "memory");
        } else {
            asm volatile("cp.async.wait_group 0;" ::: "memory");
        }
        __syncthreads();

        if (kt == 0) {
#pragma unroll
            for (int dc = 0; dc < 8; dc++) {
                uint32_t off = sb + SM_Q + (uint32_t)((wq0 + lr) * QSTR + dc * 16 + lc) * 2;
                ldsm_x4(off, qf[dc][0], qf[dc][1], qf[dc][2], qf[dc][3]);
            }
        }

        const uint32_t kb_ = sb + SM_K + buf * 17408;
        const uint32_t vb_ = sb + SM_VT + buf * 36864;

        float s[4][2][4];
#pragma unroll
        for (int g = 0; g < 4; g++)
#pragma unroll
            for (int p = 0; p < 2; p++)
#pragma unroll
                for (int c = 0; c < 4; c++) s[g][p][c] = 0.f;
#pragma unroll
        for (int dc = 0; dc < 8; dc++)
#pragma unroll
            for (int g = 0; g < 4; g++) {
                uint32_t kbt[4];
                ldsm_x4(kb_ + (uint32_t)((g * 16 + lr) * QSTR + dc * 16 + lc) * 2,
                        kbt[0], kbt[1], kbt[2], kbt[3]);
                mma_bf16(s[g][0], qf[dc], kbt[0], kbt[2]);
                mma_bf16(s[g][1], qf[dc], kbt[1], kbt[3]);
            }

        if (kt >= 2 * qb) {
#pragma unroll
            for (int g = 0; g < 4; g++)
#pragma unroll
                for (int p = 0; p < 2; p++) {
                    int key = kt * 64 + g * 16 + p * 8 + gc;
                    if (key > q_row0)     s[g][p][0] = MASKV;
                    if (key + 1 > q_row0) s[g][p][1] = MASKV;
                    if (key > q_row0 + 8)     s[g][p][2] = MASKV;
                    if (key + 1 > q_row0 + 8) s[g][p][3] = MASKV;
                }
        }

        float t0 = MASKV, t1 = MASKV;
#pragma unroll
        for (int g = 0; g < 4; g++)
#pragma unroll
            for (int p = 0; p < 2; p++) {
                t0 = fmaxf(t0, fmaxf(s[g][p][0], s[g][p][1]));
                t1 = fmaxf(t1, fmaxf(s[g][p][2], s[g][p][3]));
            }
        t0 = fmaxf(t0, __shfl_xor_sync(0xffffffffu, t0, 1));
        t0 = fmaxf(t0, __shfl_xor_sync(0xffffffffu, t0, 2));
        t1 = fmaxf(t1, __shfl_xor_sync(0xffffffffu, t1, 1));
        t1 = fmaxf(t1, __shfl_xor_sync(0xffffffffu, t1, 2));
        float mn0 = fmaxf(m0, t0), mn1 = fmaxf(m1, t1);
        float a0 = ex2f((m0 - mn0) * CEXP), a1 = ex2f((m1 - mn1) * CEXP);
        m0 = mn0; m1 = mn1;

        uint32_t pah[4][4], pal[4][4];
        float sum0 = 0.f, sum1 = 0.f;
#pragma unroll
        for (int g = 0; g < 4; g++)
#pragma unroll
            for (int p = 0; p < 2; p++) {
                float p0 = ex2f((s[g][p][0] - mn0) * CEXP);
                float p1 = ex2f((s[g][p][1] - mn0) * CEXP);
                float p2 = ex2f((s[g][p][2] - mn1) * CEXP);
                float p3 = ex2f((s[g][p][3] - mn1) * CEXP);
                sum0 += p0 + p1; sum1 += p2 + p3;
                pah[g][2 * p]     = pack2bf(p0, p1);
                pah[g][2 * p + 1] = pack2bf(p2, p3);
                pal[g][2 * p]     = pack2bf(p0 - bf_hi_f(p0), p1 - bf_hi_f(p1));
                pal[g][2 * p + 1] = pack2bf(p2 - bf_hi_f(p2), p3 - bf_hi_f(p3));
            }
        sum0 += __shfl_xor_sync(0xffffffffu, sum0, 1);
        sum0 += __shfl_xor_sync(0xffffffffu, sum0, 2);
        sum1 += __shfl_xor_sync(0xffffffffu, sum1, 1);
        sum1 += __shfl_xor_sync(0xffffffffu, sum1, 2);
        l0 = l0 * a0 + sum0;
        l1 = l1 * a1 + sum1;

#pragma unroll
        for (int gd = 0; gd < 8; gd++)
#pragma unroll
            for (int p = 0; p < 2; p++) {
                acc_o[gd][p][0] *= a0; acc_o[gd][p][1] *= a0;
                acc_o[gd][p][2] *= a1; acc_o[gd][p][3] *= a1;
            }

#pragma unroll
        for (int kc = 0; kc < 4; kc++)
#pragma unroll
            for (int gd = 0; gd < 8; gd++) {
                uint32_t off = (uint32_t)((gd * 16 + lr) * VTSTR + kc * 16 + lc) * 2;
                uint32_t bvh[4], bvl[4];
                ldsm_x4(vb_ + off, bvh[0], bvh[1], bvh[2], bvh[3]);
                ldsm_x4(vb_ + 18432 + off, bvl[0], bvl[1], bvl[2], bvl[3]);
                mma_bf16(acc_o[gd][0], pah[kc], bvh[0], bvh[2]);
                mma_bf16(acc_o[gd][1], pah[kc], bvh[1], bvh[3]);
                mma_bf16(acc_o[gd][0], pah[kc], bvl[0], bvl[2]);
                mma_bf16(acc_o[gd][1], pah[kc], bvl[1], bvl[3]);
                mma_bf16(acc_o[gd][0], pal[kc], bvh[0], bvh[2]);
                mma_bf16(acc_o[gd][1], pal[kc], bvh[1], bvh[3]);
            }
        __syncthreads();
    }

    const float i0 = 1.f / l0, i1 = 1.f / l1;
    const size_t tok0 = (size_t)b * SEQ + qb * 128 + wq0 + gr;
#pragma unroll
    for (int gd = 0; gd < 8; gd++)
#pragma unroll
        for (int p = 0; p < 2; p++) {
            int col = h * HD + gd * 16 + p * 8 + gc;
            float v0 = acc_o[gd][p][0] * i0, v1 = acc_o[gd][p][1] * i0;
            float v2 = acc_o[gd][p][2] * i1, v3 = acc_o[gd][p][3] * i1;
            size_t o0 = tok0 * DMODEL + col, o1 = (tok0 + 8) * DMODEL + col;
            *(uint32_t*)&ath[o0] = pack2bf(v0, v1);
            *(uint32_t*)&atl[o0] = pack2bf(v0 - bf_hi_f(v0), v1 - bf_hi_f(v1));
            *(uint32_t*)&ath[o1] = pack2bf(v2, v3);
            *(uint32_t*)&atl[o1] = pack2bf(v2 - bf_hi_f(v2), v3 - bf_hi_f(v3));
        }
}

// ---------------------------------------------------------------------------
extern "C" void kernel_launch(void* const* d_in, const int* in_sizes, int n_in,
                              void* d_out, int out_size)
{
    const float* x    = (const float*)d_in[0];
    const float* Wqkv = (const float*)d_in[1];
    const float* Wo   = (const float*)d_in[2];
    float* out = (float*)d_out;

    void* p;
    cudaGetSymbolAddress(&p, g_xh);    __nv_bfloat16* xh = (__nv_bfloat16*)p;
    cudaGetSymbolAddress(&p, g_xl);    __nv_bfloat16* xl = (__nv_bfloat16*)p;
    cudaGetSymbolAddress(&p, g_wqkvh); __nv_bfloat16* wqh = (__nv_bfloat16*)p;
    cudaGetSymbolAddress(&p, g_wqkvl); __nv_bfloat16* wql = (__nv_bfloat16*)p;
    cudaGetSymbolAddress(&p, g_woh);   __nv_bfloat16* woh = (__nv_bfloat16*)p;
    cudaGetSymbolAddress(&p, g_wol);   __nv_bfloat16* wol = (__nv_bfloat16*)p;
    cudaGetSymbolAddress(&p, g_qkvh);  __nv_bfloat16* qvh = (__nv_bfloat16*)p;
    cudaGetSymbolAddress(&p, g_qkvl);  __nv_bfloat16* qvl = (__nv_bfloat16*)p;
    cudaGetSymbolAddress(&p, g_vth);   __nv_bfloat16* vth = (__nv_bfloat16*)p;
    cudaGetSymbolAddress(&p, g_vtl);   __nv_bfloat16* vtl = (__nv_bfloat16*)p;
    cudaGetSymbolAddress(&p, g_ath);   __nv_bfloat16* ath = (__nv_bfloat16*)p;
    cudaGetSymbolAddress(&p, g_atl);   __nv_bfloat16* atl = (__nv_bfloat16*)p;

    cudaFuncSetAttribute(gemm_mma<true, 1>, cudaFuncAttributeMaxDynamicSharedMemorySize,
                         GEMM1_SMEM);
    cudaFuncSetAttribute(gemm_mma<true, 3>, cudaFuncAttributeMaxDynamicSharedMemorySize,
                         GEMM3_SMEM);
    cudaFuncSetAttribute(gemm_mma<false, 3>, cudaFuncAttributeMaxDynamicSharedMemorySize,
                         GEMM3_SMEM);
    cudaFuncSetAttribute(attn_mma, cudaFuncAttributeMaxDynamicSharedMemorySize,
                         ATTN_SMEM_BYTES);

    // 0) split inputs
    split_kernel<<<(NR * DMODEL / 4 + 255) / 256, 256>>>(x, xh, xl, NR * DMODEL / 4);
    split_kernel<<<(TDMODEL * DMODEL / 4 + 255) / 256, 256>>>(Wqkv, wqh, wql,
                                                              TDMODEL * DMODEL / 4);
    split_kernel<<<(DMODEL * DMODEL / 4 + 255) / 256, 256>>>(Wo, woh, wol,
                                                             DMODEL * DMODEL / 4);

    // 1a) Q,K projection: single-pass bf16
    gemm_mma<true, 1><<<dim3(2 * DMODEL / 128, NR / 128), 256, GEMM1_SMEM>>>(
        xh, xl, wqh, wql, nullptr, qvh, qvl, TDMODEL, DMODEL);

    // 1b) V projection: 3-pass split
    gemm_mma<true, 3><<<dim3(DMODEL / 128, NR / 128), 256, GEMM3_SMEM>>>(
        xh, xl, wqh + (size_t)2 * DMODEL * DMODEL, wql + (size_t)2 * DMODEL * DMODEL,
        nullptr, qvh + 2 * DMODEL, qvl + 2 * DMODEL, TDMODEL, DMODEL);

    // 2) transpose V panels
    vtrans_kernel<<<dim3(SEQ / 32, HD / 32, NB * NH), dim3(32, 8)>>>(
        (const ushort*)qvh, (const ushort*)qvl, (ushort*)vth, (ushort*)vtl);

    // 3) attention -> bf16 hi/lo
    attn_mma<<<dim3(16, NH, NB), 256, ATTN_SMEM_BYTES>>>(qvh, vth, vtl, ath, atl);

    // 4) out = att @ Wo^T (fp32 out, 3-pass)
    gemm_mma<false, 3><<<dim3(DMODEL / 128, NR / 128), 256, GEMM3_SMEM>>>(
        ath, atl, woh, wol, out, nullptr, nullptr, DMODEL, DMODEL);
}